// round 13
// baseline (speedup 1.0000x reference)
#include <cuda_runtime.h>
#include <cuda_bf16.h>
#include <math.h>

// Problem constants
#define HD 256          // hidden dim
#define GG 768          // 3*H gates
#define NV 50000        // vocabulary size
#define NVT ((NV + 127) / 128)   // vocab tiles of 128 rows (391)
#define NSENT 2048      // R*S sentences
#define NWORD 64        // words per sentence
#define NREV 64         // reviews
#define SPR 32          // sentences per review
#define DREV 276        // H + UF
#define DREVP 288       // padded
#define UF 20

typedef unsigned long long u64;
typedef unsigned int u32;
typedef unsigned short u16;

// ---------------- scratch (static device arrays; no allocation allowed) ----------------
__device__ float g_sgT_ih[2 * 256 * GG];
__device__ float g_sgT_hh[2 * 256 * GG];
__device__ float g_rgT_ih[2 * DREVP * GG];
__device__ float g_rgT_hh[2 * 256 * GG];
__device__ __nv_bfloat16 g_wih_hi[2 * GG * 256];   // split-bf16 word Wih (native [g][k])
__device__ __nv_bfloat16 g_wih_lo[2 * GG * 256];
__device__ u32 g_whhF_hi[2 * 96 * 16 * 32 * 2];    // fragment-major split Whh (hi)
__device__ u32 g_whhF_lo[2 * 96 * 16 * 32 * 2];    // fragment-major split Whh (lo)
__device__ float g_bias_comb[2 * GG];              // bih + (g<512 ? bhh : 0)
__device__ float g_gx_v[(size_t)2 * NV * GG];      // per-VOCAB input-gates (307 MB)
__device__ float g_gx_s[2 * NSENT * GG];
__device__ float g_gx_r[2 * NREV * GG];
__device__ float g_sent[2 * NSENT * HD];
__device__ float g_rev[2 * NREV * HD];
__device__ float g_pbatch[NREV * DREV];
__device__ float g_doc[2 * HD];

// ---------------- helpers ----------------
__device__ __forceinline__ float sigf(float x) { return 1.0f / (1.0f + __expf(-x)); }

__device__ __forceinline__ float seluf(float x) {
    const float alpha = 1.6732632423543772f;
    const float scale = 1.0507009873554805f;
    return x > 0.0f ? scale * x : scale * alpha * (expf(x) - 1.0f);
}

__device__ __forceinline__ u64 pack2(float lo, float hi) {
    u64 r; asm("mov.b64 %0, {%1, %2};" : "=l"(r) : "f"(lo), "f"(hi)); return r;
}
__device__ __forceinline__ void unpack2(u64 v, float& lo, float& hi) {
    asm("mov.b64 {%0, %1}, %2;" : "=f"(lo), "=f"(hi) : "l"(v));
}
__device__ __forceinline__ u64 fma2(u64 a, u64 b, u64 c) {
    u64 d; asm("fma.rn.f32x2 %0, %1, %2, %3;" : "=l"(d) : "l"(a), "l"(b), "l"(c)); return d;
}
__device__ __forceinline__ u32 smem_u32(const void* p) {
    u32 a; asm("{ .reg .u64 t; cvta.to.shared.u64 t, %1; cvt.u32.u64 %0, t; }" : "=r"(a) : "l"(p));
    return a;
}

// ---------------- baseline-PTX tensor core wrappers (sm_80+) ----------
__device__ __forceinline__ void ldm_x4(u32& r0, u32& r1, u32& r2, u32& r3, u32 addr) {
    asm volatile("ldmatrix.sync.aligned.m8n8.x4.shared.b16 {%0,%1,%2,%3}, [%4];"
                 : "=r"(r0), "=r"(r1), "=r"(r2), "=r"(r3) : "r"(addr));
}
__device__ __forceinline__ void mma_bf16(float* d, const u32* a, u32 b0, u32 b1) {
    asm volatile("mma.sync.aligned.m16n8k16.row.col.f32.bf16.bf16.f32 "
                 "{%0,%1,%2,%3}, {%4,%5,%6,%7}, {%8,%9}, {%0,%1,%2,%3};"
                 : "+f"(d[0]), "+f"(d[1]), "+f"(d[2]), "+f"(d[3])
                 : "r"(a[0]), "r"(a[1]), "r"(a[2]), "r"(a[3]), "r"(b0), "r"(b1));
}

// split fp32 -> (hi, lo) bf16
__device__ __forceinline__ void bf_split(float x, u16& hb, u16& lb) {
    __nv_bfloat16 h = __float2bfloat16_rn(x);
    float r = x - __bfloat162float(h);
    __nv_bfloat16 l = __float2bfloat16_rn(r);
    hb = __bfloat16_as_ushort(h);
    lb = __bfloat16_as_ushort(l);
}

// ---------------- prep 1: sg transposes + rg transposes ----------------
__global__ void prep1_kernel(const float* __restrict__ sg_wih, float* __restrict__ sgTih,
                             const float* __restrict__ sg_whh, float* __restrict__ sgThh,
                             const float* __restrict__ rg_wih, float* __restrict__ rgTih,
                             const float* __restrict__ rg_whh, float* __restrict__ rgThh) {
    const int nA = 2 * GG * 256;
    const int nB = 2 * DREVP * GG;
    int idx = blockIdx.x * blockDim.x + threadIdx.x;
    if (idx < nA) {
        int g = idx % GG; int rem = idx / GG; int k = rem % 256; int d = rem / 256;
        sgTih[idx] = sg_wih[((size_t)d * GG + g) * 256 + k];
    } else if (idx < 2 * nA) {
        int j = idx - nA;
        int g = j % GG; int rem = j / GG; int k = rem % 256; int d = rem / 256;
        sgThh[j] = sg_whh[((size_t)d * GG + g) * 256 + k];
    } else if (idx < 3 * nA) {
        int j = idx - 2 * nA;
        int g = j % GG; int rem = j / GG; int k = rem % 256; int d = rem / 256;
        rgThh[j] = rg_whh[((size_t)d * GG + g) * 256 + k];
    } else if (idx < 3 * nA + nB) {
        int j = idx - 3 * nA;
        int g = j % GG; int rem = j / GG; int k = rem % DREVP; int d = rem / DREVP;
        rgTih[j] = (k < DREV) ? rg_wih[((size_t)d * GG + g) * DREV + k] : 0.0f;
    }
}

// ---------------- prep 2: wih split + Whh fragment-major split + combined bias ----------
__global__ void prep2_kernel(const float* __restrict__ wg_wih,
                             __nv_bfloat16* __restrict__ wihhi,
                             __nv_bfloat16* __restrict__ wihlo,
                             const float* __restrict__ wg_whh,
                             u32* __restrict__ whhFhi, u32* __restrict__ whhFlo,
                             const float* __restrict__ wg_bih,
                             const float* __restrict__ wg_bhh,
                             float* __restrict__ bias_comb) {
    const int nW = 2 * GG * 256;
    const int nF = 2 * 96 * 16 * 32 * 2;
    int idx = blockIdx.x * blockDim.x + threadIdx.x;
    if (idx < nW) {
        u16 hb, lb;
        bf_split(wg_wih[idx], hb, lb);
        wihhi[idx] = __ushort_as_bfloat16(hb);
        wihlo[idx] = __ushort_as_bfloat16(lb);
    } else if (idx < nW + nF) {
        int i = idx - nW;
        int p    = i & 1;
        int lane = (i >> 1) & 31;
        int ks   = (i >> 6) & 15;
        int rest = i >> 10;
        int gt   = rest % 96;
        int dir  = rest / 96;
        int g = gt * 8 + (lane >> 2);
        int k = ks * 16 + 2 * (lane & 3) + p * 8;
        float w0 = wg_whh[((size_t)dir * GG + g) * 256 + k];
        float w1 = wg_whh[((size_t)dir * GG + g) * 256 + k + 1];
        u16 h0, l0, h1, l1;
        bf_split(w0, h0, l0); bf_split(w1, h1, l1);
        whhFhi[i] = (u32)h0 | ((u32)h1 << 16);
        whhFlo[i] = (u32)l0 | ((u32)l1 << 16);
    } else if (idx < nW + nF + 2 * GG) {
        int j = idx - nW - nF;
        int g = j % GG;
        bias_comb[j] = wg_bih[j] + (g < 512 ? wg_bhh[j] : 0.0f);
    }
}

// ================= HMMA (mma.sync) vocab input-gate GEMM =================
#define ASTRIDE 264
#define OFF_AHI 0
#define OFF_ALO (128 * ASTRIDE)
#define OFF_BHI (2 * 128 * ASTRIDE)
#define OFF_BLO (2 * 128 * ASTRIDE + 64 * ASTRIDE)
#define SMTOT   ((2 * 128 * ASTRIDE + 2 * 64 * ASTRIDE) * 2)   // 202752 bytes

__global__ __launch_bounds__(256)
void vocab_gemm_mma(const float* __restrict__ embed,
                    const __nv_bfloat16* __restrict__ whi,
                    const __nv_bfloat16* __restrict__ wlo,
                    const float* __restrict__ bias,
                    float* __restrict__ gxv) {
    extern __shared__ __nv_bfloat16 sm[];
    __nv_bfloat16* Ahi = sm + OFF_AHI;
    __nv_bfloat16* Alo = sm + OFF_ALO;
    __nv_bfloat16* Bhi = sm + OFF_BHI;
    __nv_bfloat16* Blo = sm + OFF_BLO;

    const int dir  = blockIdx.y;
    const int row0 = blockIdx.x * 128;
    const int tid  = threadIdx.x;
    const int lane = tid & 31;
    const int warp = tid >> 5;

    for (int i = tid; i < 128 * 64; i += 256) {
        int r = i >> 6, q = i & 63;
        int vr = row0 + r; if (vr >= NV) vr = NV - 1;
        float4 v = __ldg(reinterpret_cast<const float4*>(embed + (size_t)vr * HD) + q);
        u16 h0, l0, h1, l1, h2, l2, h3, l3;
        bf_split(v.x, h0, l0); bf_split(v.y, h1, l1);
        bf_split(v.z, h2, l2); bf_split(v.w, h3, l3);
        uint2 ph = make_uint2((u32)h0 | ((u32)h1 << 16), (u32)h2 | ((u32)h3 << 16));
        uint2 pl = make_uint2((u32)l0 | ((u32)l1 << 16), (u32)l2 | ((u32)l3 << 16));
        *reinterpret_cast<uint2*>(Ahi + r * ASTRIDE + q * 4) = ph;
        *reinterpret_cast<uint2*>(Alo + r * ASTRIDE + q * 4) = pl;
    }
    __syncthreads();

    const u32 aRow = warp * 16 + (lane & 15);
    const u32 aK8  = (u32)(lane >> 4) << 3;
    const u32 aHiAddr = smem_u32(Ahi + aRow * ASTRIDE + aK8);
    const u32 aLoAddr = smem_u32(Alo + aRow * ASTRIDE + aK8);
    const u32 bRow = ((u32)(lane >> 4) << 3) + (lane & 7);
    const u32 bK8  = ((u32)(lane >> 3) & 1) << 3;
    const u32 bHiAddr = smem_u32(Bhi + bRow * ASTRIDE + bK8);
    const u32 bLoAddr = smem_u32(Blo + bRow * ASTRIDE + bK8);

    const int r0 = row0 + warp * 16 + (lane >> 2);

#pragma unroll 1
    for (int ch = 0; ch < 12; ch++) {
        {
            const __nv_bfloat16* srch = whi + ((size_t)dir * GG + ch * 64) * 256;
            const __nv_bfloat16* srcl = wlo + ((size_t)dir * GG + ch * 64) * 256;
            for (int i = tid; i < 64 * 32; i += 256) {
                int r = i >> 5, q = i & 31;
                *reinterpret_cast<uint4*>(Bhi + r * ASTRIDE + q * 8) =
                    reinterpret_cast<const uint4*>(srch + (size_t)r * 256)[q];
                *reinterpret_cast<uint4*>(Blo + r * ASTRIDE + q * 8) =
                    reinterpret_cast<const uint4*>(srcl + (size_t)r * 256)[q];
            }
        }
        __syncthreads();

        float acc[8][4];
#pragma unroll
        for (int n = 0; n < 8; n++) { acc[n][0] = acc[n][1] = acc[n][2] = acc[n][3] = 0.0f; }

#pragma unroll 1
        for (int ks = 0; ks < 16; ks++) {
            u32 ah[4], al[4];
            ldm_x4(ah[0], ah[1], ah[2], ah[3], aHiAddr + ks * 32);
            ldm_x4(al[0], al[1], al[2], al[3], aLoAddr + ks * 32);
#pragma unroll
            for (int p = 0; p < 4; p++) {
                u32 bh[4], bl[4];
                const u32 boff = (u32)(p * 16) * (ASTRIDE * 2) + ks * 32;
                ldm_x4(bh[0], bh[1], bh[2], bh[3], bHiAddr + boff);
                ldm_x4(bl[0], bl[1], bl[2], bl[3], bLoAddr + boff);
                mma_bf16(acc[2 * p],     ah, bh[0], bh[1]);
                mma_bf16(acc[2 * p],     ah, bl[0], bl[1]);
                mma_bf16(acc[2 * p],     al, bh[0], bh[1]);
                mma_bf16(acc[2 * p + 1], ah, bh[2], bh[3]);
                mma_bf16(acc[2 * p + 1], ah, bl[2], bl[3]);
                mma_bf16(acc[2 * p + 1], al, bh[2], bh[3]);
            }
        }
        __syncthreads();

        const int gbase = ch * 64 + 2 * (lane & 3);
#pragma unroll
        for (int nt = 0; nt < 8; nt++) {
            const int g = gbase + nt * 8;
            const float b0 = __ldg(bias + dir * GG + g);
            const float b1 = __ldg(bias + dir * GG + g + 1);
            if (r0 < NV) {
                float2 o = make_float2(acc[nt][0] + b0, acc[nt][1] + b1);
                *reinterpret_cast<float2*>(gxv + ((size_t)dir * NV + r0) * GG + g) = o;
            }
            if (r0 + 8 < NV) {
                float2 o = make_float2(acc[nt][2] + b0, acc[nt][3] + b1);
                *reinterpret_cast<float2*>(gxv + ((size_t)dir * NV + r0 + 8) * GG + g) = o;
            }
        }
    }
}

// ================= tensorized word-level recurrent GRU (512 threads) =================
// 32 batch rows per CTA, 16 warps = 2 rowgroups(16) x 8 colgroups (12 gate-tiles each).
// Whh streamed as pre-permuted mma fragments (coalesced LDG.64, software-pipelined).
#define RSTR 264
#define SM_HHI 0
#define SM_HLO (32 * RSTR * 2)
#define SM_HFP (2 * 32 * RSTR * 2)
#define SM_REC_TOT (2 * 32 * RSTR * 2 + 32 * RSTR * 4)   // 67584 bytes

__global__ __launch_bounds__(512)
void word_rec_mma(const int* __restrict__ widx,
                  const float* __restrict__ gxv,
                  const u32* __restrict__ whhFhi,
                  const u32* __restrict__ whhFlo,
                  const float* __restrict__ wg_bhh,
                  float* __restrict__ sent) {
    extern __shared__ char smraw[];
    __nv_bfloat16* hhi = reinterpret_cast<__nv_bfloat16*>(smraw + SM_HHI);
    __nv_bfloat16* hlo = reinterpret_cast<__nv_bfloat16*>(smraw + SM_HLO);
    float*         hfp = reinterpret_cast<float*>(smraw + SM_HFP);

    const int dir  = blockIdx.y;
    const int row0 = blockIdx.x * 32;
    const int tid  = threadIdx.x;
    const int lane = tid & 31;
    const int warp = tid >> 5;
    const int rg   = warp >> 3;      // 0..1
    const int cg   = warp & 7;       // 0..7

    for (int i = tid; i < SM_REC_TOT / 4; i += 512)
        reinterpret_cast<u32*>(smraw)[i] = 0u;
    __syncthreads();

    const u32 aRow = rg * 16 + (lane & 15);
    const u32 aK8  = (u32)(lane >> 4) << 3;
    const u32 aHiAddr = smem_u32(hhi + aRow * RSTR + aK8);
    const u32 aLoAddr = smem_u32(hlo + aRow * RSTR + aK8);

    const int rowA = rg * 16 + (lane >> 2);
    const int rowB = rowA + 8;
    const int* wrA = widx + (row0 + rowA) * NWORD;
    const int* wrB = widx + (row0 + rowB) * NWORD;
    const float* bhhn = wg_bhh + dir * GG + 512;

    const char* fHi = reinterpret_cast<const char*>(whhFhi) + (size_t)dir * 96 * 16 * 256 + lane * 8;
    const char* fLo = reinterpret_cast<const char*>(whhFlo) + (size_t)dir * 96 * 16 * 256 + lane * 8;

    for (int t = 0; t < NWORD; t++) {
        const int te = dir ? (NWORD - 1 - t) : t;

        float acc[6][2][4];
#pragma unroll
        for (int c = 0; c < 6; c++)
#pragma unroll
            for (int n = 0; n < 2; n++)
                acc[c][n][0] = acc[c][n][1] = acc[c][n][2] = acc[c][n][3] = 0.0f;

        // ---- MMA: gates += h @ WhhT (3-term split-bf16), B pipelined over ks ----
#pragma unroll
        for (int c = 0; c < 6; c++) {
            const int gt0 = c * 16 + cg * 2;   // this warp's 2 gate-tiles for chunk c
            const char* f0h = fHi + (size_t)gt0 * 16 * 256;
            const char* f1h = f0h + (size_t)16 * 256;
            const char* f0l = fLo + (size_t)gt0 * 16 * 256;
            const char* f1l = f0l + (size_t)16 * 256;

            u64 pbh[2][2], pbl[2][2];   // [buf][nt]
            pbh[0][0] = *reinterpret_cast<const u64*>(f0h);
            pbh[0][1] = *reinterpret_cast<const u64*>(f1h);
            pbl[0][0] = *reinterpret_cast<const u64*>(f0l);
            pbl[0][1] = *reinterpret_cast<const u64*>(f1l);

#pragma unroll
            for (int ks = 0; ks < 16; ks++) {
                const int cur = ks & 1, nxt = cur ^ 1;
                if (ks < 15) {
                    const size_t o = (size_t)(ks + 1) * 256;
                    pbh[nxt][0] = *reinterpret_cast<const u64*>(f0h + o);
                    pbh[nxt][1] = *reinterpret_cast<const u64*>(f1h + o);
                    pbl[nxt][0] = *reinterpret_cast<const u64*>(f0l + o);
                    pbl[nxt][1] = *reinterpret_cast<const u64*>(f1l + o);
                }
                u32 ah[4], al[4];
                ldm_x4(ah[0], ah[1], ah[2], ah[3], aHiAddr + ks * 32);
                ldm_x4(al[0], al[1], al[2], al[3], aLoAddr + ks * 32);
#pragma unroll
                for (int nt = 0; nt < 2; nt++) {
                    const u32 bh0 = (u32)pbh[cur][nt], bh1 = (u32)(pbh[cur][nt] >> 32);
                    const u32 bl0 = (u32)pbl[cur][nt], bl1 = (u32)(pbl[cur][nt] >> 32);
                    mma_bf16(acc[c][nt], ah, bh0, bh1);
                    mma_bf16(acc[c][nt], ah, bl0, bl1);
                    mma_bf16(acc[c][nt], al, bh0, bh1);
                }
            }
        }
        __syncthreads();   // all warps done reading h smem

        // ---- epilogue: gate nonlinearity + h update ----
        const int va = wrA[te], vb = wrB[te];
        const float* gA = gxv + ((size_t)dir * NV + va) * GG;
        const float* gB = gxv + ((size_t)dir * NV + vb) * GG;

#pragma unroll
        for (int c = 0; c < 2; c++) {
#pragma unroll
            for (int nt = 0; nt < 2; nt++) {
                const int d = c * 128 + cg * 16 + nt * 8 + 2 * (lane & 3);
                const float2 bn = *reinterpret_cast<const float2*>(bhhn + d);
                // row A
                {
                    float2 xr = *reinterpret_cast<const float2*>(gA + d);
                    float2 xz = *reinterpret_cast<const float2*>(gA + 256 + d);
                    float2 xn = *reinterpret_cast<const float2*>(gA + 512 + d);
                    float r0 = sigf(xr.x + acc[c][nt][0]);
                    float r1 = sigf(xr.y + acc[c][nt][1]);
                    float z0 = sigf(xz.x + acc[c + 2][nt][0]);
                    float z1 = sigf(xz.y + acc[c + 2][nt][1]);
                    float n0 = tanhf(xn.x + r0 * (acc[c + 4][nt][0] + bn.x));
                    float n1 = tanhf(xn.y + r1 * (acc[c + 4][nt][1] + bn.y));
                    float* hp = hfp + rowA * RSTR + d;
                    float h0 = (1.0f - z0) * n0 + z0 * hp[0];
                    float h1 = (1.0f - z1) * n1 + z1 * hp[1];
                    hp[0] = h0; hp[1] = h1;
                    u16 hh0, hl0, hh1, hl1;
                    bf_split(h0, hh0, hl0); bf_split(h1, hh1, hl1);
                    *reinterpret_cast<u32*>(hhi + rowA * RSTR + d) = (u32)hh0 | ((u32)hh1 << 16);
                    *reinterpret_cast<u32*>(hlo + rowA * RSTR + d) = (u32)hl0 | ((u32)hl1 << 16);
                }
                // row B
                {
                    float2 xr = *reinterpret_cast<const float2*>(gB + d);
                    float2 xz = *reinterpret_cast<const float2*>(gB + 256 + d);
                    float2 xn = *reinterpret_cast<const float2*>(gB + 512 + d);
                    float r0 = sigf(xr.x + acc[c][nt][2]);
                    float r1 = sigf(xr.y + acc[c][nt][3]);
                    float z0 = sigf(xz.x + acc[c + 2][nt][2]);
                    float z1 = sigf(xz.y + acc[c + 2][nt][3]);
                    float n0 = tanhf(xn.x + r0 * (acc[c + 4][nt][2] + bn.x));
                    float n1 = tanhf(xn.y + r1 * (acc[c + 4][nt][3] + bn.y));
                    float* hp = hfp + rowB * RSTR + d;
                    float h0 = (1.0f - z0) * n0 + z0 * hp[0];
                    float h1 = (1.0f - z1) * n1 + z1 * hp[1];
                    hp[0] = h0; hp[1] = h1;
                    u16 hh0, hl0, hh1, hl1;
                    bf_split(h0, hh0, hl0); bf_split(h1, hh1, hl1);
                    *reinterpret_cast<u32*>(hhi + rowB * RSTR + d) = (u32)hh0 | ((u32)hh1 << 16);
                    *reinterpret_cast<u32*>(hlo + rowB * RSTR + d) = (u32)hl0 | ((u32)hl1 << 16);
                }
            }
        }
        __syncthreads();   // h updated before next step's reads
    }

    for (int i = tid; i < 32 * HD; i += 512) {
        int r = i >> 8, d = i & 255;
        sent[((size_t)dir * NSENT + row0 + r) * HD + d] = hfp[r * RSTR + d];
    }
}

// ---------------- FFMA2 input-gates GEMM (sentence / review levels) ----------------
template <int U>
__device__ __forceinline__ void load_wchunk(float (&w)[3][U], const float* __restrict__ base, int kb) {
#pragma unroll
    for (int u = 0; u < U; u++) {
        const float* p = base + (size_t)(kb + u) * GG;
        w[0][u] = __ldg(p);
        w[1][u] = __ldg(p + 256);
        w[2][u] = __ldg(p + 512);
    }
}

template <int U, int P, int K>
__device__ __forceinline__ void fma_chunk(u64 (&acc)[P][3], const float (&w)[3][U],
                                          const float2 (*sx)[K], int kb) {
#pragma unroll
    for (int u = 0; u < U; u++) {
        const u64 w0p = pack2(w[0][u], w[0][u]);
        const u64 w1p = pack2(w[1][u], w[1][u]);
        const u64 w2p = pack2(w[2][u], w[2][u]);
#pragma unroll
        for (int p = 0; p < P; p++) {
            const u64 xp = *reinterpret_cast<const u64*>(&sx[p][kb + u]);
            acc[p][0] = fma2(xp, w0p, acc[p][0]);
            acc[p][1] = fma2(xp, w1p, acc[p][1]);
            acc[p][2] = fma2(xp, w2p, acc[p][2]);
        }
    }
}

// MODE 1: x = xin0[row]+xin1[row] (sentence level)
// MODE 2: x = xin0[row]  (review level, true K = KD, padded to K)
template <int MODE, int K, int KD, int TOKS>
__global__ __launch_bounds__(256, 2)
void gates_gemm_kernel(const float* __restrict__ xin0,
                       const float* __restrict__ xin1,
                       const float* __restrict__ wT_ih,
                       const float* __restrict__ bih,
                       float* __restrict__ gx, int M) {
    constexpr int P = TOKS / 2;
    constexpr int U = 4;
    const int dir  = blockIdx.y;
    const int tok0 = blockIdx.x * TOKS;
    const int t0   = threadIdx.x;

    __shared__ float2 sx2[P][K];

#pragma unroll
    for (int p = 0; p < P; p++) {
        const int ta = tok0 + 2 * p, tb = ta + 1;
        for (int k = t0; k < K; k += 256) {
            float xa, xb;
            if (MODE == 1) {
                xa = xin0[(size_t)ta * HD + k] + xin1[(size_t)ta * HD + k];
                xb = xin0[(size_t)tb * HD + k] + xin1[(size_t)tb * HD + k];
            } else {
                xa = (k < KD) ? xin0[(size_t)ta * KD + k] : 0.0f;
                xb = (k < KD) ? xin0[(size_t)tb * KD + k] : 0.0f;
            }
            sx2[p][k] = make_float2(xa, xb);
        }
    }
    __syncthreads();

    const float* wbase = wT_ih + (size_t)dir * K * GG + t0;
    u64 acc[P][3];
#pragma unroll
    for (int p = 0; p < P; p++) acc[p][0] = acc[p][1] = acc[p][2] = 0ull;

    float wA[3][U], wB[3][U];
    load_wchunk<U>(wA, wbase, 0);
#pragma unroll 1
    for (int kb = 0; kb < K; kb += 2 * U) {
        load_wchunk<U>(wB, wbase, kb + U);
        fma_chunk<U, P, K>(acc, wA, sx2, kb);
        if (kb + 2 * U < K) load_wchunk<U>(wA, wbase, kb + 2 * U);
        fma_chunk<U, P, K>(acc, wB, sx2, kb + U);
    }

    const float bi0 = bih[dir * GG + t0];
    const float bi1 = bih[dir * GG + 256 + t0];
    const float bi2 = bih[dir * GG + 512 + t0];
#pragma unroll
    for (int p = 0; p < P; p++) {
        float a0, b0, a1, b1, a2, b2;
        unpack2(acc[p][0], a0, b0);
        unpack2(acc[p][1], a1, b1);
        unpack2(acc[p][2], a2, b2);
        float* oa = gx + ((size_t)dir * M + tok0 + 2 * p) * GG;
        float* ob = oa + GG;
        oa[t0]       = a0 + bi0;  ob[t0]       = b0 + bi0;
        oa[256 + t0] = a1 + bi1;  ob[256 + t0] = b1 + bi1;
        oa[512 + t0] = a2 + bi2;  ob[512 + t0] = b2 + bi2;
    }
}

// ---------------- sentence-level recurrent GRU, row-paired f32x2 ----------------
template <int ROWS, int T>
__global__ __launch_bounds__(256, 2)
void gru_rec_kernel(const float* __restrict__ gx, int gxM,
                    const float* __restrict__ wT_hh,
                    const float* __restrict__ bhh,
                    float* __restrict__ out, int nbatch) {
    constexpr int P = ROWS / 2;
    constexpr int U = 4;
    const int dir  = blockIdx.y;
    const int row0 = blockIdx.x * ROWS;
    const int t0   = threadIdx.x;

    __shared__ float2 sh2[P][HD];
#pragma unroll
    for (int p = 0; p < P; p++) sh2[p][t0] = make_float2(0.0f, 0.0f);

    const float* wbase = wT_hh + (size_t)dir * HD * GG + t0;
    const float bh0 = bhh[dir * GG + t0];
    const float bh1 = bhh[dir * GG + 256 + t0];
    const float bh2 = bhh[dir * GG + 512 + t0];
    __syncthreads();

    for (int t = 0; t < T; t++) {
        const int te = dir ? (T - 1 - t) : t;

        u64 ah[P][3];
#pragma unroll
        for (int p = 0; p < P; p++) ah[p][0] = ah[p][1] = ah[p][2] = 0ull;

        float wA[3][U], wB[3][U];
        load_wchunk<U>(wA, wbase, 0);
#pragma unroll 1
        for (int kb = 0; kb < HD; kb += 2 * U) {
            load_wchunk<U>(wB, wbase, kb + U);
            fma_chunk<U, P, HD>(ah, wA, sh2, kb);
            if (kb + 2 * U < HD) load_wchunk<U>(wA, wbase, kb + 2 * U);
            fma_chunk<U, P, HD>(ah, wB, sh2, kb + U);
        }
        __syncthreads();

#pragma unroll
        for (int p = 0; p < P; p++) {
            const int ra = row0 + 2 * p, rb = ra + 1;
            const float* ga = gx + ((size_t)dir * gxM + (size_t)ra * T + te) * GG;
            const float* gb = gx + ((size_t)dir * gxM + (size_t)rb * T + te) * GG;
            const float x0a = ga[t0], x1a = ga[256 + t0], x2a = ga[512 + t0];
            const float x0b = gb[t0], x1b = gb[256 + t0], x2b = gb[512 + t0];
            float h0a, h0b, h1a, h1b, h2a, h2b;
            unpack2(ah[p][0], h0a, h0b); unpack2(ah[p][1], h1a, h1b); unpack2(ah[p][2], h2a, h2b);
            const float2 hold = sh2[p][t0];
            const float rga = sigf(x0a + h0a + bh0), rgb = sigf(x0b + h0b + bh0);
            const float za  = sigf(x1a + h1a + bh1), zb  = sigf(x1b + h1b + bh1);
            const float na  = tanhf(x2a + rga * (h2a + bh2));
            const float nb  = tanhf(x2b + rgb * (h2b + bh2));
            sh2[p][t0] = make_float2((1.0f - za) * na + za * hold.x,
                                     (1.0f - zb) * nb + zb * hold.y);
        }
        __syncthreads();
    }

#pragma unroll
    for (int p = 0; p < P; p++) {
        const float2 h = sh2[p][t0];
        out[((size_t)dir * nbatch + row0 + 2 * p) * HD + t0]     = h.x;
        out[((size_t)dir * nbatch + row0 + 2 * p + 1) * HD + t0] = h.y;
    }
}

// ---------------- review-level recurrent GRU (batch 1, 768 threads) -------
__global__ __launch_bounds__(768)
void gru_rec1_kernel(const float* __restrict__ gx,
                     const float* __restrict__ wT_hh,
                     const float* __restrict__ bhh,
                     float* __restrict__ out) {
    const int dir = blockIdx.x;
    const int g   = threadIdx.x;
    __shared__ float sh[HD];
    __shared__ float acc[GG];
    if (g < HD) sh[g] = 0.0f;
    const float* whh = wT_hh + (size_t)dir * HD * GG + g;
    const float bh = bhh[dir * GG + g];
    __syncthreads();

    for (int t = 0; t < NREV; t++) {
        const int te = dir ? (NREV - 1 - t) : t;
        float a = 0.0f;
#pragma unroll 8
        for (int k = 0; k < HD; k++) a += sh[k] * whh[(size_t)k * GG];
        acc[g] = a + bh;
        __syncthreads();
        if (g < HD) {
            const float* ga = gx + ((size_t)dir * NREV + te) * GG;
            const float r = sigf(ga[g]       + acc[g]);
            const float z = sigf(ga[256 + g] + acc[256 + g]);
            const float n = tanhf(ga[512 + g] + r * acc[512 + g]);
            sh[g] = (1.0f - z) * n + z * sh[g];
        }
        __syncthreads();
    }
    if (g < HD) out[dir * HD + g] = sh[g];
}

// ---------------- p_batch / heads ----------------
__global__ void pbatch_kernel(const float* __restrict__ rev0,
                              const float* __restrict__ rev1,
                              const float* __restrict__ user_feats,
                              const float* __restrict__ uf_w,
                              float* __restrict__ pbatch) {
    int b = blockIdx.x;
    int t = threadIdx.x;
    if (t < HD) {
        pbatch[b * DREV + t] = rev0[b * HD + t] + rev1[b * HD + t];
    } else {
        int lane = t - HD;
        float v = (lane < UF) ? user_feats[b * UF + lane] : 0.0f;
        float s = v * v;
#pragma unroll
        for (int o = 16; o > 0; o >>= 1) s += __shfl_xor_sync(0xffffffffu, s, o);
        float nrm = fmaxf(sqrtf(s), 1e-12f);
        if (lane < UF) pbatch[b * DREV + HD + lane] = (v / nrm) * uf_w[lane];
    }
}

__global__ void rstars_kernel(const float* __restrict__ pbatch,
                              const float* __restrict__ w1, const float* __restrict__ b1,
                              const float* __restrict__ w2, const float* __restrict__ b2,
                              float* __restrict__ out) {
    int b = blockIdx.x;
    int j = threadIdx.x;
    float s = b1[j];
    for (int k = 0; k < DREV; k++) s += pbatch[b * DREV + k] * w1[j * DREV + k];
    float a = seluf(s) * w2[j];
    __shared__ float red[128];
    red[j] = a;
    __syncthreads();
    for (int st = 64; st > 0; st >>= 1) {
        if (j < st) red[j] += red[j + st];
        __syncthreads();
    }
    if (j == 0) out[9 + b] = red[0] + b2[0];
}

__global__ void pstars_kernel(const float* __restrict__ doc,
                              const float* __restrict__ w1, const float* __restrict__ b1,
                              const float* __restrict__ w2, const float* __restrict__ b2,
                              float* __restrict__ out) {
    int j = threadIdx.x;
    __shared__ float hid[128];
    float s = b1[j];
    for (int k = 0; k < HD; k++) s += (doc[k] + doc[HD + k]) * w1[j * HD + k];
    hid[j] = seluf(s);
    __syncthreads();
    if (j < 9) {
        float o = b2[j];
        for (int k = 0; k < 128; k++) o += hid[k] * w2[j * 128 + k];
        out[j] = o;
    }
}

// ---------------- launch ----------------
extern "C" void kernel_launch(void* const* d_in, const int* in_sizes, int n_in,
                              void* d_out, int out_size) {
    (void)in_sizes; (void)n_in; (void)out_size;
    const int*   inputs     = (const int*)d_in[0];
    const float* user_feats = (const float*)d_in[3];
    const float* embed      = (const float*)d_in[4];
    const float* wg_wih = (const float*)d_in[5];
    const float* wg_whh = (const float*)d_in[6];
    const float* wg_bih = (const float*)d_in[7];
    const float* wg_bhh = (const float*)d_in[8];
    const float* sg_wih = (const float*)d_in[9];
    const float* sg_whh = (const float*)d_in[10];
    const float* sg_bih = (const float*)d_in[11];
    const float* sg_bhh = (const float*)d_in[12];
    const float* rg_wih = (const float*)d_in[13];
    const float* rg_whh = (const float*)d_in[14];
    const float* rg_bih = (const float*)d_in[15];
    const float* rg_bhh = (const float*)d_in[16];
    const float* rfc_w1 = (const float*)d_in[17];
    const float* rfc_b1 = (const float*)d_in[18];
    const float* rfc_w2 = (const float*)d_in[19];
    const float* rfc_b2 = (const float*)d_in[20];
    const float* pfc_w1 = (const float*)d_in[21];
    const float* pfc_b1 = (const float*)d_in[22];
    const float* pfc_w2 = (const float*)d_in[23];
    const float* pfc_b2 = (const float*)d_in[24];
    const float* uf_w   = (const float*)d_in[25];
    float* out = (float*)d_out;

    float *sgTih, *sgThh, *rgTih, *rgThh, *bias_comb;
    float *gxv, *gxs, *gxr, *sent, *rev, *pbatch, *doc;
    __nv_bfloat16 *wihhi, *wihlo;
    u32 *whhFhi, *whhFlo;
    cudaGetSymbolAddress((void**)&sgTih, g_sgT_ih);
    cudaGetSymbolAddress((void**)&sgThh, g_sgT_hh);
    cudaGetSymbolAddress((void**)&rgTih, g_rgT_ih);
    cudaGetSymbolAddress((void**)&rgThh, g_rgT_hh);
    cudaGetSymbolAddress((void**)&wihhi, g_wih_hi);
    cudaGetSymbolAddress((void**)&wihlo, g_wih_lo);
    cudaGetSymbolAddress((void**)&whhFhi, g_whhF_hi);
    cudaGetSymbolAddress((void**)&whhFlo, g_whhF_lo);
    cudaGetSymbolAddress((void**)&bias_comb, g_bias_comb);
    cudaGetSymbolAddress((void**)&gxv,   g_gx_v);
    cudaGetSymbolAddress((void**)&gxs,   g_gx_s);
    cudaGetSymbolAddress((void**)&gxr,   g_gx_r);
    cudaGetSymbolAddress((void**)&sent,  g_sent);
    cudaGetSymbolAddress((void**)&rev,   g_rev);
    cudaGetSymbolAddress((void**)&pbatch,g_pbatch);
    cudaGetSymbolAddress((void**)&doc,   g_doc);

    cudaFuncSetAttribute(vocab_gemm_mma, cudaFuncAttributeMaxDynamicSharedMemorySize, SMTOT);
    cudaFuncSetAttribute(word_rec_mma, cudaFuncAttributeMaxDynamicSharedMemorySize, SM_REC_TOT);

    // prep — 2 launches so word_rec_mma is our launch #4 (profiled by ncu -s 5)
    {
        int n1 = 3 * (2 * GG * 256) + 2 * DREVP * GG;
        prep1_kernel<<<(n1 + 255) / 256, 256>>>(sg_wih, sgTih, sg_whh, sgThh,
                                                rg_wih, rgTih, rg_whh, rgThh);   // launch 1
        int n2 = 2 * GG * 256 + 2 * 96 * 16 * 32 * 2 + 2 * GG;
        prep2_kernel<<<(n2 + 255) / 256, 256>>>(wg_wih, wihhi, wihlo,
                                                wg_whh, whhFhi, whhFlo,
                                                wg_bih, wg_bhh, bias_comb);      // launch 2
    }

    // word level: HMMA vocab gates (launch 3), then tensorized recurrent (launch 4)
    vocab_gemm_mma<<<dim3(NVT, 2), 256, SMTOT>>>(embed, wihhi, wihlo, bias_comb, gxv);
    word_rec_mma<<<dim3(NSENT / 32, 2), 512, SM_REC_TOT>>>(
        inputs, gxv, whhFhi, whhFlo, wg_bhh, sent);

    // sentence level
    gates_gemm_kernel<1, 256, 256, 16><<<dim3(NSENT / 16, 2), 256>>>(
        sent, sent + NSENT * HD, sgTih, sg_bih, gxs, NSENT);
    gru_rec_kernel<2, SPR><<<dim3(NREV / 2, 2), 256>>>(
        gxs, NSENT, sgThh, sg_bhh, rev, NREV);

    // p_batch + r_stars head
    pbatch_kernel<<<NREV, 288>>>(rev, rev + NREV * HD, user_feats, uf_w, pbatch);
    rstars_kernel<<<NREV, 128>>>(pbatch, rfc_w1, rfc_b1, rfc_w2, rfc_b2, out);

    // review level
    gates_gemm_kernel<2, DREVP, DREV, 16><<<dim3(NREV / 16, 2), 256>>>(
        pbatch, nullptr, rgTih, rg_bih, gxr, NREV);
    gru_rec1_kernel<<<2, 768>>>(gxr, rgThh, rg_bhh, doc);

    // p_stars head
    pstars_kernel<<<1, 128>>>(doc, pfc_w1, pfc_b1, pfc_w2, pfc_b2, out);
}

// round 14
// speedup vs baseline: 1.4203x; 1.4203x over previous
#include <cuda_runtime.h>
#include <cuda_bf16.h>
#include <math.h>

// Problem constants
#define HD 256          // hidden dim
#define GG 768          // 3*H gates
#define NV 50000        // vocabulary size
#define NVT ((NV + 127) / 128)   // vocab tiles of 128 rows (391)
#define NSENT 2048      // R*S sentences
#define NWORD 64        // words per sentence
#define NREV 64         // reviews
#define SPR 32          // sentences per review
#define DREV 276        // H + UF
#define DREVP 288       // padded
#define UF 20

typedef unsigned long long u64;
typedef unsigned int u32;
typedef unsigned short u16;

// ---------------- scratch (static device arrays; no allocation allowed) ----------------
__device__ float g_sgT_ih[2 * 256 * GG];
__device__ float g_sgT_hh[2 * 256 * GG];
__device__ float g_rgT_ih[2 * DREVP * GG];
__device__ float g_rgT_hh[2 * 256 * GG];
__device__ __nv_bfloat16 g_wih_hi[2 * GG * 256];   // split-bf16 word Wih (native [g][k])
__device__ __nv_bfloat16 g_wih_lo[2 * GG * 256];
__device__ u32 g_whhF_hi[2 * 96 * 16 * 32 * 2];    // fragment-major split Whh (hi)
__device__ u32 g_whhF_lo[2 * 96 * 16 * 32 * 2];    // fragment-major split Whh (lo)
__device__ float g_bias_comb[2 * GG];              // bih + (g<512 ? bhh : 0)
__device__ float g_gx_v[(size_t)2 * NV * GG];      // per-VOCAB input-gates (307 MB)
__device__ float g_gx_s[2 * NSENT * GG];
__device__ float g_gx_r[2 * NREV * GG];
__device__ float g_sent[2 * NSENT * HD];
__device__ float g_rev[2 * NREV * HD];
__device__ float g_pbatch[NREV * DREV];
__device__ float g_doc[2 * HD];

// ---------------- helpers ----------------
__device__ __forceinline__ float sigf(float x) { return 1.0f / (1.0f + __expf(-x)); }

__device__ __forceinline__ float seluf(float x) {
    const float alpha = 1.6732632423543772f;
    const float scale = 1.0507009873554805f;
    return x > 0.0f ? scale * x : scale * alpha * (expf(x) - 1.0f);
}

__device__ __forceinline__ u64 pack2(float lo, float hi) {
    u64 r; asm("mov.b64 %0, {%1, %2};" : "=l"(r) : "f"(lo), "f"(hi)); return r;
}
__device__ __forceinline__ void unpack2(u64 v, float& lo, float& hi) {
    asm("mov.b64 {%0, %1}, %2;" : "=f"(lo), "=f"(hi) : "l"(v));
}
__device__ __forceinline__ u64 fma2(u64 a, u64 b, u64 c) {
    u64 d; asm("fma.rn.f32x2 %0, %1, %2, %3;" : "=l"(d) : "l"(a), "l"(b), "l"(c)); return d;
}
__device__ __forceinline__ u32 smem_u32(const void* p) {
    u32 a; asm("{ .reg .u64 t; cvta.to.shared.u64 t, %1; cvt.u32.u64 %0, t; }" : "=r"(a) : "l"(p));
    return a;
}

// ---------------- baseline-PTX tensor core wrappers (sm_80+) ----------
__device__ __forceinline__ void ldm_x4(u32& r0, u32& r1, u32& r2, u32& r3, u32 addr) {
    asm volatile("ldmatrix.sync.aligned.m8n8.x4.shared.b16 {%0,%1,%2,%3}, [%4];"
                 : "=r"(r0), "=r"(r1), "=r"(r2), "=r"(r3) : "r"(addr));
}
__device__ __forceinline__ void mma_bf16(float* d, const u32* a, u32 b0, u32 b1) {
    asm volatile("mma.sync.aligned.m16n8k16.row.col.f32.bf16.bf16.f32 "
                 "{%0,%1,%2,%3}, {%4,%5,%6,%7}, {%8,%9}, {%0,%1,%2,%3};"
                 : "+f"(d[0]), "+f"(d[1]), "+f"(d[2]), "+f"(d[3])
                 : "r"(a[0]), "r"(a[1]), "r"(a[2]), "r"(a[3]), "r"(b0), "r"(b1));
}

// split fp32 -> (hi, lo) bf16
__device__ __forceinline__ void bf_split(float x, u16& hb, u16& lb) {
    __nv_bfloat16 h = __float2bfloat16_rn(x);
    float r = x - __bfloat162float(h);
    __nv_bfloat16 l = __float2bfloat16_rn(r);
    hb = __bfloat16_as_ushort(h);
    lb = __bfloat16_as_ushort(l);
}

// ---------------- prep 1: sg transposes + rg transposes ----------------
__global__ void prep1_kernel(const float* __restrict__ sg_wih, float* __restrict__ sgTih,
                             const float* __restrict__ sg_whh, float* __restrict__ sgThh,
                             const float* __restrict__ rg_wih, float* __restrict__ rgTih,
                             const float* __restrict__ rg_whh, float* __restrict__ rgThh) {
    const int nA = 2 * GG * 256;
    const int nB = 2 * DREVP * GG;
    int idx = blockIdx.x * blockDim.x + threadIdx.x;
    if (idx < nA) {
        int g = idx % GG; int rem = idx / GG; int k = rem % 256; int d = rem / 256;
        sgTih[idx] = sg_wih[((size_t)d * GG + g) * 256 + k];
    } else if (idx < 2 * nA) {
        int j = idx - nA;
        int g = j % GG; int rem = j / GG; int k = rem % 256; int d = rem / 256;
        sgThh[j] = sg_whh[((size_t)d * GG + g) * 256 + k];
    } else if (idx < 3 * nA) {
        int j = idx - 2 * nA;
        int g = j % GG; int rem = j / GG; int k = rem % 256; int d = rem / 256;
        rgThh[j] = rg_whh[((size_t)d * GG + g) * 256 + k];
    } else if (idx < 3 * nA + nB) {
        int j = idx - 3 * nA;
        int g = j % GG; int rem = j / GG; int k = rem % DREVP; int d = rem / DREVP;
        rgTih[j] = (k < DREV) ? rg_wih[((size_t)d * GG + g) * DREV + k] : 0.0f;
    }
}

// ---------------- prep 2: wih split + Whh fragment-major split + combined bias ----------
__global__ void prep2_kernel(const float* __restrict__ wg_wih,
                             __nv_bfloat16* __restrict__ wihhi,
                             __nv_bfloat16* __restrict__ wihlo,
                             const float* __restrict__ wg_whh,
                             u32* __restrict__ whhFhi, u32* __restrict__ whhFlo,
                             const float* __restrict__ wg_bih,
                             const float* __restrict__ wg_bhh,
                             float* __restrict__ bias_comb) {
    const int nW = 2 * GG * 256;
    const int nF = 2 * 96 * 16 * 32 * 2;
    int idx = blockIdx.x * blockDim.x + threadIdx.x;
    if (idx < nW) {
        u16 hb, lb;
        bf_split(wg_wih[idx], hb, lb);
        wihhi[idx] = __ushort_as_bfloat16(hb);
        wihlo[idx] = __ushort_as_bfloat16(lb);
    } else if (idx < nW + nF) {
        int i = idx - nW;
        int p    = i & 1;
        int lane = (i >> 1) & 31;
        int ks   = (i >> 6) & 15;
        int rest = i >> 10;
        int gt   = rest % 96;
        int dir  = rest / 96;
        int g = gt * 8 + (lane >> 2);
        int k = ks * 16 + 2 * (lane & 3) + p * 8;
        float w0 = wg_whh[((size_t)dir * GG + g) * 256 + k];
        float w1 = wg_whh[((size_t)dir * GG + g) * 256 + k + 1];
        u16 h0, l0, h1, l1;
        bf_split(w0, h0, l0); bf_split(w1, h1, l1);
        whhFhi[i] = (u32)h0 | ((u32)h1 << 16);
        whhFlo[i] = (u32)l0 | ((u32)l1 << 16);
    } else if (idx < nW + nF + 2 * GG) {
        int j = idx - nW - nF;
        int g = j % GG;
        bias_comb[j] = wg_bih[j] + (g < 512 ? wg_bhh[j] : 0.0f);
    }
}

// ================= HMMA (mma.sync) vocab input-gate GEMM =================
#define ASTRIDE 264
#define OFF_AHI 0
#define OFF_ALO (128 * ASTRIDE)
#define OFF_BHI (2 * 128 * ASTRIDE)
#define OFF_BLO (2 * 128 * ASTRIDE + 64 * ASTRIDE)
#define SMTOT   ((2 * 128 * ASTRIDE + 2 * 64 * ASTRIDE) * 2)   // 202752 bytes

__global__ __launch_bounds__(256)
void vocab_gemm_mma(const float* __restrict__ embed,
                    const __nv_bfloat16* __restrict__ whi,
                    const __nv_bfloat16* __restrict__ wlo,
                    const float* __restrict__ bias,
                    float* __restrict__ gxv) {
    extern __shared__ __nv_bfloat16 sm[];
    __nv_bfloat16* Ahi = sm + OFF_AHI;
    __nv_bfloat16* Alo = sm + OFF_ALO;
    __nv_bfloat16* Bhi = sm + OFF_BHI;
    __nv_bfloat16* Blo = sm + OFF_BLO;

    const int dir  = blockIdx.y;
    const int row0 = blockIdx.x * 128;
    const int tid  = threadIdx.x;
    const int lane = tid & 31;
    const int warp = tid >> 5;

    for (int i = tid; i < 128 * 64; i += 256) {
        int r = i >> 6, q = i & 63;
        int vr = row0 + r; if (vr >= NV) vr = NV - 1;
        float4 v = __ldg(reinterpret_cast<const float4*>(embed + (size_t)vr * HD) + q);
        u16 h0, l0, h1, l1, h2, l2, h3, l3;
        bf_split(v.x, h0, l0); bf_split(v.y, h1, l1);
        bf_split(v.z, h2, l2); bf_split(v.w, h3, l3);
        uint2 ph = make_uint2((u32)h0 | ((u32)h1 << 16), (u32)h2 | ((u32)h3 << 16));
        uint2 pl = make_uint2((u32)l0 | ((u32)l1 << 16), (u32)l2 | ((u32)l3 << 16));
        *reinterpret_cast<uint2*>(Ahi + r * ASTRIDE + q * 4) = ph;
        *reinterpret_cast<uint2*>(Alo + r * ASTRIDE + q * 4) = pl;
    }
    __syncthreads();

    const u32 aRow = warp * 16 + (lane & 15);
    const u32 aK8  = (u32)(lane >> 4) << 3;
    const u32 aHiAddr = smem_u32(Ahi + aRow * ASTRIDE + aK8);
    const u32 aLoAddr = smem_u32(Alo + aRow * ASTRIDE + aK8);
    const u32 bRow = ((u32)(lane >> 4) << 3) + (lane & 7);
    const u32 bK8  = ((u32)(lane >> 3) & 1) << 3;
    const u32 bHiAddr = smem_u32(Bhi + bRow * ASTRIDE + bK8);
    const u32 bLoAddr = smem_u32(Blo + bRow * ASTRIDE + bK8);

    const int r0 = row0 + warp * 16 + (lane >> 2);

#pragma unroll 1
    for (int ch = 0; ch < 12; ch++) {
        {
            const __nv_bfloat16* srch = whi + ((size_t)dir * GG + ch * 64) * 256;
            const __nv_bfloat16* srcl = wlo + ((size_t)dir * GG + ch * 64) * 256;
            for (int i = tid; i < 64 * 32; i += 256) {
                int r = i >> 5, q = i & 31;
                *reinterpret_cast<uint4*>(Bhi + r * ASTRIDE + q * 8) =
                    reinterpret_cast<const uint4*>(srch + (size_t)r * 256)[q];
                *reinterpret_cast<uint4*>(Blo + r * ASTRIDE + q * 8) =
                    reinterpret_cast<const uint4*>(srcl + (size_t)r * 256)[q];
            }
        }
        __syncthreads();

        float acc[8][4];
#pragma unroll
        for (int n = 0; n < 8; n++) { acc[n][0] = acc[n][1] = acc[n][2] = acc[n][3] = 0.0f; }

#pragma unroll 1
        for (int ks = 0; ks < 16; ks++) {
            u32 ah[4], al[4];
            ldm_x4(ah[0], ah[1], ah[2], ah[3], aHiAddr + ks * 32);
            ldm_x4(al[0], al[1], al[2], al[3], aLoAddr + ks * 32);
#pragma unroll
            for (int p = 0; p < 4; p++) {
                u32 bh[4], bl[4];
                const u32 boff = (u32)(p * 16) * (ASTRIDE * 2) + ks * 32;
                ldm_x4(bh[0], bh[1], bh[2], bh[3], bHiAddr + boff);
                ldm_x4(bl[0], bl[1], bl[2], bl[3], bLoAddr + boff);
                mma_bf16(acc[2 * p],     ah, bh[0], bh[1]);
                mma_bf16(acc[2 * p],     ah, bl[0], bl[1]);
                mma_bf16(acc[2 * p],     al, bh[0], bh[1]);
                mma_bf16(acc[2 * p + 1], ah, bh[2], bh[3]);
                mma_bf16(acc[2 * p + 1], ah, bl[2], bl[3]);
                mma_bf16(acc[2 * p + 1], al, bh[2], bh[3]);
            }
        }
        __syncthreads();

        const int gbase = ch * 64 + 2 * (lane & 3);
#pragma unroll
        for (int nt = 0; nt < 8; nt++) {
            const int g = gbase + nt * 8;
            const float b0 = __ldg(bias + dir * GG + g);
            const float b1 = __ldg(bias + dir * GG + g + 1);
            if (r0 < NV) {
                float2 o = make_float2(acc[nt][0] + b0, acc[nt][1] + b1);
                *reinterpret_cast<float2*>(gxv + ((size_t)dir * NV + r0) * GG + g) = o;
            }
            if (r0 + 8 < NV) {
                float2 o = make_float2(acc[nt][2] + b0, acc[nt][3] + b1);
                *reinterpret_cast<float2*>(gxv + ((size_t)dir * NV + r0 + 8) * GG + g) = o;
            }
        }
    }
}

// ================= tensorized word-level recurrent GRU (512 threads, v3) =================
// 32 batch rows per CTA; 16 warps, warp w owns hidden dims [16w, 16w+16) across r/z/n
// (6 gate tiles: gt = grp*32 + 2w + j) x BOTH 16-row A-tiles -> every Whh fragment is
// loaded exactly once per CTA per step.  ks-outer loop: A fragments reused across all
// 6 gate tiles; 12 independent accumulator chains; B register-double-buffered over ks.
#define RSTR 264
#define SM_HHI 0
#define SM_HLO (32 * RSTR * 2)
#define SM_HFP (2 * 32 * RSTR * 2)
#define SM_REC_TOT (2 * 32 * RSTR * 2 + 32 * RSTR * 4)   // 67584 bytes

__global__ __launch_bounds__(512)
void word_rec_mma(const int* __restrict__ widx,
                  const float* __restrict__ gxv,
                  const u32* __restrict__ whhFhi,
                  const u32* __restrict__ whhFlo,
                  const float* __restrict__ wg_bhh,
                  float* __restrict__ sent) {
    extern __shared__ char smraw[];
    __nv_bfloat16* hhi = reinterpret_cast<__nv_bfloat16*>(smraw + SM_HHI);
    __nv_bfloat16* hlo = reinterpret_cast<__nv_bfloat16*>(smraw + SM_HLO);
    float*         hfp = reinterpret_cast<float*>(smraw + SM_HFP);

    const int dir  = blockIdx.y;
    const int row0 = blockIdx.x * 32;
    const int tid  = threadIdx.x;
    const int lane = tid & 31;
    const int warp = tid >> 5;   // 0..15

    for (int i = tid; i < SM_REC_TOT / 4; i += 512)
        reinterpret_cast<u32*>(smraw)[i] = 0u;
    __syncthreads();

    // A ldmatrix addresses for the two 16-row tiles
    const u32 aK8 = (u32)(lane >> 4) << 3;
    const u32 aHi0 = smem_u32(hhi + ((lane & 15)) * RSTR + aK8);
    const u32 aLo0 = smem_u32(hlo + ((lane & 15)) * RSTR + aK8);
    const u32 aHi1 = smem_u32(hhi + (16 + (lane & 15)) * RSTR + aK8);
    const u32 aLo1 = smem_u32(hlo + (16 + (lane & 15)) * RSTR + aK8);

    // B fragment warp base: gt = grp*32 + 2*warp + j -> byte off grp*131072 + j*4096 (+ks*256)
    const char* fWhi = reinterpret_cast<const char*>(whhFhi)
                       + (size_t)dir * 96 * 4096 + (size_t)warp * 8192 + lane * 8;
    const char* fWlo = reinterpret_cast<const char*>(whhFlo)
                       + (size_t)dir * 96 * 4096 + (size_t)warp * 8192 + lane * 8;

    const float* bhhn = wg_bhh + dir * GG + 512;
    const int dbase = 16 * warp + 2 * (lane & 3);
    const float2 bn0 = *reinterpret_cast<const float2*>(bhhn + dbase);
    const float2 bn1 = *reinterpret_cast<const float2*>(bhhn + dbase + 8);

    for (int t = 0; t < NWORD; t++) {
        const int te = dir ? (NWORD - 1 - t) : t;

        float acc[3][2][2][4];   // [grp][j][atile][frag]
#pragma unroll
        for (int g = 0; g < 3; g++)
#pragma unroll
            for (int j = 0; j < 2; j++)
#pragma unroll
                for (int a = 0; a < 2; a++)
                    acc[g][j][a][0] = acc[g][j][a][1] = acc[g][j][a][2] = acc[g][j][a][3] = 0.0f;

        u64 pb[2][12];
        // preload ks = 0
#pragma unroll
        for (int g = 0; g < 3; g++)
#pragma unroll
            for (int j = 0; j < 2; j++) {
                const size_t off = (size_t)g * 131072 + (size_t)j * 4096;
                pb[0][g * 4 + j * 2]     = *reinterpret_cast<const u64*>(fWhi + off);
                pb[0][g * 4 + j * 2 + 1] = *reinterpret_cast<const u64*>(fWlo + off);
            }

#pragma unroll
        for (int ks = 0; ks < 16; ks++) {
            const int cur = ks & 1, nxt = cur ^ 1;
            if (ks < 15) {
#pragma unroll
                for (int g = 0; g < 3; g++)
#pragma unroll
                    for (int j = 0; j < 2; j++) {
                        const size_t off = (size_t)g * 131072 + (size_t)j * 4096
                                         + (size_t)(ks + 1) * 256;
                        pb[nxt][g * 4 + j * 2]     = *reinterpret_cast<const u64*>(fWhi + off);
                        pb[nxt][g * 4 + j * 2 + 1] = *reinterpret_cast<const u64*>(fWlo + off);
                    }
            }
            u32 ah0[4], al0[4], ah1[4], al1[4];
            ldm_x4(ah0[0], ah0[1], ah0[2], ah0[3], aHi0 + ks * 32);
            ldm_x4(al0[0], al0[1], al0[2], al0[3], aLo0 + ks * 32);
            ldm_x4(ah1[0], ah1[1], ah1[2], ah1[3], aHi1 + ks * 32);
            ldm_x4(al1[0], al1[1], al1[2], al1[3], aLo1 + ks * 32);
#pragma unroll
            for (int g = 0; g < 3; g++)
#pragma unroll
                for (int j = 0; j < 2; j++) {
                    const u64 bh = pb[cur][g * 4 + j * 2];
                    const u64 bl = pb[cur][g * 4 + j * 2 + 1];
                    const u32 bh0 = (u32)bh, bh1 = (u32)(bh >> 32);
                    const u32 bl0 = (u32)bl, bl1 = (u32)(bl >> 32);
                    mma_bf16(acc[g][j][0], ah0, bh0, bh1);
                    mma_bf16(acc[g][j][0], ah0, bl0, bl1);
                    mma_bf16(acc[g][j][0], al0, bh0, bh1);
                    mma_bf16(acc[g][j][1], ah1, bh0, bh1);
                    mma_bf16(acc[g][j][1], ah1, bl0, bl1);
                    mma_bf16(acc[g][j][1], al1, bh0, bh1);
                }
        }
        __syncthreads();   // all warps done reading h smem

        // ---- epilogue: gate nonlinearity + h update ----
#pragma unroll
        for (int a = 0; a < 2; a++) {
#pragma unroll
            for (int p = 0; p < 2; p++) {
                const int row = a * 16 + (lane >> 2) + p * 8;
                const int v = __ldg(widx + (row0 + row) * NWORD + te);
                const float* gp = gxv + ((size_t)dir * NV + v) * GG;
#pragma unroll
                for (int j = 0; j < 2; j++) {
                    const int d = dbase + 8 * j;
                    const float2 bn = j ? bn1 : bn0;
                    float2 xr = *reinterpret_cast<const float2*>(gp + d);
                    float2 xz = *reinterpret_cast<const float2*>(gp + 256 + d);
                    float2 xn = *reinterpret_cast<const float2*>(gp + 512 + d);
                    float r0 = sigf(xr.x + acc[0][j][a][2 * p]);
                    float r1 = sigf(xr.y + acc[0][j][a][2 * p + 1]);
                    float z0 = sigf(xz.x + acc[1][j][a][2 * p]);
                    float z1 = sigf(xz.y + acc[1][j][a][2 * p + 1]);
                    float n0 = tanhf(xn.x + r0 * (acc[2][j][a][2 * p] + bn.x));
                    float n1 = tanhf(xn.y + r1 * (acc[2][j][a][2 * p + 1] + bn.y));
                    float* hp = hfp + row * RSTR + d;
                    float h0 = (1.0f - z0) * n0 + z0 * hp[0];
                    float h1 = (1.0f - z1) * n1 + z1 * hp[1];
                    hp[0] = h0; hp[1] = h1;
                    u16 hh0, hl0, hh1, hl1;
                    bf_split(h0, hh0, hl0); bf_split(h1, hh1, hl1);
                    *reinterpret_cast<u32*>(hhi + row * RSTR + d) = (u32)hh0 | ((u32)hh1 << 16);
                    *reinterpret_cast<u32*>(hlo + row * RSTR + d) = (u32)hl0 | ((u32)hl1 << 16);
                }
            }
        }
        __syncthreads();   // h updated before next step's reads
    }

    for (int i = tid; i < 32 * HD; i += 512) {
        int r = i >> 8, d = i & 255;
        sent[((size_t)dir * NSENT + row0 + r) * HD + d] = hfp[r * RSTR + d];
    }
}

// ---------------- FFMA2 input-gates GEMM (sentence / review levels) ----------------
template <int U>
__device__ __forceinline__ void load_wchunk(float (&w)[3][U], const float* __restrict__ base, int kb) {
#pragma unroll
    for (int u = 0; u < U; u++) {
        const float* p = base + (size_t)(kb + u) * GG;
        w[0][u] = __ldg(p);
        w[1][u] = __ldg(p + 256);
        w[2][u] = __ldg(p + 512);
    }
}

template <int U, int P, int K>
__device__ __forceinline__ void fma_chunk(u64 (&acc)[P][3], const float (&w)[3][U],
                                          const float2 (*sx)[K], int kb) {
#pragma unroll
    for (int u = 0; u < U; u++) {
        const u64 w0p = pack2(w[0][u], w[0][u]);
        const u64 w1p = pack2(w[1][u], w[1][u]);
        const u64 w2p = pack2(w[2][u], w[2][u]);
#pragma unroll
        for (int p = 0; p < P; p++) {
            const u64 xp = *reinterpret_cast<const u64*>(&sx[p][kb + u]);
            acc[p][0] = fma2(xp, w0p, acc[p][0]);
            acc[p][1] = fma2(xp, w1p, acc[p][1]);
            acc[p][2] = fma2(xp, w2p, acc[p][2]);
        }
    }
}

// MODE 1: x = xin0[row]+xin1[row] (sentence level)
// MODE 2: x = xin0[row]  (review level, true K = KD, padded to K)
template <int MODE, int K, int KD, int TOKS>
__global__ __launch_bounds__(256, 2)
void gates_gemm_kernel(const float* __restrict__ xin0,
                       const float* __restrict__ xin1,
                       const float* __restrict__ wT_ih,
                       const float* __restrict__ bih,
                       float* __restrict__ gx, int M) {
    constexpr int P = TOKS / 2;
    constexpr int U = 4;
    const int dir  = blockIdx.y;
    const int tok0 = blockIdx.x * TOKS;
    const int t0   = threadIdx.x;

    __shared__ float2 sx2[P][K];

#pragma unroll
    for (int p = 0; p < P; p++) {
        const int ta = tok0 + 2 * p, tb = ta + 1;
        for (int k = t0; k < K; k += 256) {
            float xa, xb;
            if (MODE == 1) {
                xa = xin0[(size_t)ta * HD + k] + xin1[(size_t)ta * HD + k];
                xb = xin0[(size_t)tb * HD + k] + xin1[(size_t)tb * HD + k];
            } else {
                xa = (k < KD) ? xin0[(size_t)ta * KD + k] : 0.0f;
                xb = (k < KD) ? xin0[(size_t)tb * KD + k] : 0.0f;
            }
            sx2[p][k] = make_float2(xa, xb);
        }
    }
    __syncthreads();

    const float* wbase = wT_ih + (size_t)dir * K * GG + t0;
    u64 acc[P][3];
#pragma unroll
    for (int p = 0; p < P; p++) acc[p][0] = acc[p][1] = acc[p][2] = 0ull;

    float wA[3][U], wB[3][U];
    load_wchunk<U>(wA, wbase, 0);
#pragma unroll 1
    for (int kb = 0; kb < K; kb += 2 * U) {
        load_wchunk<U>(wB, wbase, kb + U);
        fma_chunk<U, P, K>(acc, wA, sx2, kb);
        if (kb + 2 * U < K) load_wchunk<U>(wA, wbase, kb + 2 * U);
        fma_chunk<U, P, K>(acc, wB, sx2, kb + U);
    }

    const float bi0 = bih[dir * GG + t0];
    const float bi1 = bih[dir * GG + 256 + t0];
    const float bi2 = bih[dir * GG + 512 + t0];
#pragma unroll
    for (int p = 0; p < P; p++) {
        float a0, b0, a1, b1, a2, b2;
        unpack2(acc[p][0], a0, b0);
        unpack2(acc[p][1], a1, b1);
        unpack2(acc[p][2], a2, b2);
        float* oa = gx + ((size_t)dir * M + tok0 + 2 * p) * GG;
        float* ob = oa + GG;
        oa[t0]       = a0 + bi0;  ob[t0]       = b0 + bi0;
        oa[256 + t0] = a1 + bi1;  ob[256 + t0] = b1 + bi1;
        oa[512 + t0] = a2 + bi2;  ob[512 + t0] = b2 + bi2;
    }
}

// ---------------- sentence-level recurrent GRU, row-paired f32x2 ----------------
template <int ROWS, int T>
__global__ __launch_bounds__(256, 2)
void gru_rec_kernel(const float* __restrict__ gx, int gxM,
                    const float* __restrict__ wT_hh,
                    const float* __restrict__ bhh,
                    float* __restrict__ out, int nbatch) {
    constexpr int P = ROWS / 2;
    constexpr int U = 4;
    const int dir  = blockIdx.y;
    const int row0 = blockIdx.x * ROWS;
    const int t0   = threadIdx.x;

    __shared__ float2 sh2[P][HD];
#pragma unroll
    for (int p = 0; p < P; p++) sh2[p][t0] = make_float2(0.0f, 0.0f);

    const float* wbase = wT_hh + (size_t)dir * HD * GG + t0;
    const float bh0 = bhh[dir * GG + t0];
    const float bh1 = bhh[dir * GG + 256 + t0];
    const float bh2 = bhh[dir * GG + 512 + t0];
    __syncthreads();

    for (int t = 0; t < T; t++) {
        const int te = dir ? (T - 1 - t) : t;

        u64 ah[P][3];
#pragma unroll
        for (int p = 0; p < P; p++) ah[p][0] = ah[p][1] = ah[p][2] = 0ull;

        float wA[3][U], wB[3][U];
        load_wchunk<U>(wA, wbase, 0);
#pragma unroll 1
        for (int kb = 0; kb < HD; kb += 2 * U) {
            load_wchunk<U>(wB, wbase, kb + U);
            fma_chunk<U, P, HD>(ah, wA, sh2, kb);
            if (kb + 2 * U < HD) load_wchunk<U>(wA, wbase, kb + 2 * U);
            fma_chunk<U, P, HD>(ah, wB, sh2, kb + U);
        }
        __syncthreads();

#pragma unroll
        for (int p = 0; p < P; p++) {
            const int ra = row0 + 2 * p, rb = ra + 1;
            const float* ga = gx + ((size_t)dir * gxM + (size_t)ra * T + te) * GG;
            const float* gb = gx + ((size_t)dir * gxM + (size_t)rb * T + te) * GG;
            const float x0a = ga[t0], x1a = ga[256 + t0], x2a = ga[512 + t0];
            const float x0b = gb[t0], x1b = gb[256 + t0], x2b = gb[512 + t0];
            float h0a, h0b, h1a, h1b, h2a, h2b;
            unpack2(ah[p][0], h0a, h0b); unpack2(ah[p][1], h1a, h1b); unpack2(ah[p][2], h2a, h2b);
            const float2 hold = sh2[p][t0];
            const float rga = sigf(x0a + h0a + bh0), rgb = sigf(x0b + h0b + bh0);
            const float za  = sigf(x1a + h1a + bh1), zb  = sigf(x1b + h1b + bh1);
            const float na  = tanhf(x2a + rga * (h2a + bh2));
            const float nb  = tanhf(x2b + rgb * (h2b + bh2));
            sh2[p][t0] = make_float2((1.0f - za) * na + za * hold.x,
                                     (1.0f - zb) * nb + zb * hold.y);
        }
        __syncthreads();
    }

#pragma unroll
    for (int p = 0; p < P; p++) {
        const float2 h = sh2[p][t0];
        out[((size_t)dir * nbatch + row0 + 2 * p) * HD + t0]     = h.x;
        out[((size_t)dir * nbatch + row0 + 2 * p + 1) * HD + t0] = h.y;
    }
}

// ---------------- review-level recurrent GRU (batch 1, 768 threads) -------
__global__ __launch_bounds__(768)
void gru_rec1_kernel(const float* __restrict__ gx,
                     const float* __restrict__ wT_hh,
                     const float* __restrict__ bhh,
                     float* __restrict__ out) {
    const int dir = blockIdx.x;
    const int g   = threadIdx.x;
    __shared__ float sh[HD];
    __shared__ float acc[GG];
    if (g < HD) sh[g] = 0.0f;
    const float* whh = wT_hh + (size_t)dir * HD * GG + g;
    const float bh = bhh[dir * GG + g];
    __syncthreads();

    for (int t = 0; t < NREV; t++) {
        const int te = dir ? (NREV - 1 - t) : t;
        float a = 0.0f;
#pragma unroll 8
        for (int k = 0; k < HD; k++) a += sh[k] * whh[(size_t)k * GG];
        acc[g] = a + bh;
        __syncthreads();
        if (g < HD) {
            const float* ga = gx + ((size_t)dir * NREV + te) * GG;
            const float r = sigf(ga[g]       + acc[g]);
            const float z = sigf(ga[256 + g] + acc[256 + g]);
            const float n = tanhf(ga[512 + g] + r * acc[512 + g]);
            sh[g] = (1.0f - z) * n + z * sh[g];
        }
        __syncthreads();
    }
    if (g < HD) out[dir * HD + g] = sh[g];
}

// ---------------- p_batch / heads ----------------
__global__ void pbatch_kernel(const float* __restrict__ rev0,
                              const float* __restrict__ rev1,
                              const float* __restrict__ user_feats,
                              const float* __restrict__ uf_w,
                              float* __restrict__ pbatch) {
    int b = blockIdx.x;
    int t = threadIdx.x;
    if (t < HD) {
        pbatch[b * DREV + t] = rev0[b * HD + t] + rev1[b * HD + t];
    } else {
        int lane = t - HD;
        float v = (lane < UF) ? user_feats[b * UF + lane] : 0.0f;
        float s = v * v;
#pragma unroll
        for (int o = 16; o > 0; o >>= 1) s += __shfl_xor_sync(0xffffffffu, s, o);
        float nrm = fmaxf(sqrtf(s), 1e-12f);
        if (lane < UF) pbatch[b * DREV + HD + lane] = (v / nrm) * uf_w[lane];
    }
}

__global__ void rstars_kernel(const float* __restrict__ pbatch,
                              const float* __restrict__ w1, const float* __restrict__ b1,
                              const float* __restrict__ w2, const float* __restrict__ b2,
                              float* __restrict__ out) {
    int b = blockIdx.x;
    int j = threadIdx.x;
    float s = b1[j];
    for (int k = 0; k < DREV; k++) s += pbatch[b * DREV + k] * w1[j * DREV + k];
    float a = seluf(s) * w2[j];
    __shared__ float red[128];
    red[j] = a;
    __syncthreads();
    for (int st = 64; st > 0; st >>= 1) {
        if (j < st) red[j] += red[j + st];
        __syncthreads();
    }
    if (j == 0) out[9 + b] = red[0] + b2[0];
}

__global__ void pstars_kernel(const float* __restrict__ doc,
                              const float* __restrict__ w1, const float* __restrict__ b1,
                              const float* __restrict__ w2, const float* __restrict__ b2,
                              float* __restrict__ out) {
    int j = threadIdx.x;
    __shared__ float hid[128];
    float s = b1[j];
    for (int k = 0; k < HD; k++) s += (doc[k] + doc[HD + k]) * w1[j * HD + k];
    hid[j] = seluf(s);
    __syncthreads();
    if (j < 9) {
        float o = b2[j];
        for (int k = 0; k < 128; k++) o += hid[k] * w2[j * 128 + k];
        out[j] = o;
    }
}

// ---------------- launch ----------------
extern "C" void kernel_launch(void* const* d_in, const int* in_sizes, int n_in,
                              void* d_out, int out_size) {
    (void)in_sizes; (void)n_in; (void)out_size;
    const int*   inputs     = (const int*)d_in[0];
    const float* user_feats = (const float*)d_in[3];
    const float* embed      = (const float*)d_in[4];
    const float* wg_wih = (const float*)d_in[5];
    const float* wg_whh = (const float*)d_in[6];
    const float* wg_bih = (const float*)d_in[7];
    const float* wg_bhh = (const float*)d_in[8];
    const float* sg_wih = (const float*)d_in[9];
    const float* sg_whh = (const float*)d_in[10];
    const float* sg_bih = (const float*)d_in[11];
    const float* sg_bhh = (const float*)d_in[12];
    const float* rg_wih = (const float*)d_in[13];
    const float* rg_whh = (const float*)d_in[14];
    const float* rg_bih = (const float*)d_in[15];
    const float* rg_bhh = (const float*)d_in[16];
    const float* rfc_w1 = (const float*)d_in[17];
    const float* rfc_b1 = (const float*)d_in[18];
    const float* rfc_w2 = (const float*)d_in[19];
    const float* rfc_b2 = (const float*)d_in[20];
    const float* pfc_w1 = (const float*)d_in[21];
    const float* pfc_b1 = (const float*)d_in[22];
    const float* pfc_w2 = (const float*)d_in[23];
    const float* pfc_b2 = (const float*)d_in[24];
    const float* uf_w   = (const float*)d_in[25];
    float* out = (float*)d_out;

    float *sgTih, *sgThh, *rgTih, *rgThh, *bias_comb;
    float *gxv, *gxs, *gxr, *sent, *rev, *pbatch, *doc;
    __nv_bfloat16 *wihhi, *wihlo;
    u32 *whhFhi, *whhFlo;
    cudaGetSymbolAddress((void**)&sgTih, g_sgT_ih);
    cudaGetSymbolAddress((void**)&sgThh, g_sgT_hh);
    cudaGetSymbolAddress((void**)&rgTih, g_rgT_ih);
    cudaGetSymbolAddress((void**)&rgThh, g_rgT_hh);
    cudaGetSymbolAddress((void**)&wihhi, g_wih_hi);
    cudaGetSymbolAddress((void**)&wihlo, g_wih_lo);
    cudaGetSymbolAddress((void**)&whhFhi, g_whhF_hi);
    cudaGetSymbolAddress((void**)&whhFlo, g_whhF_lo);
    cudaGetSymbolAddress((void**)&bias_comb, g_bias_comb);
    cudaGetSymbolAddress((void**)&gxv,   g_gx_v);
    cudaGetSymbolAddress((void**)&gxs,   g_gx_s);
    cudaGetSymbolAddress((void**)&gxr,   g_gx_r);
    cudaGetSymbolAddress((void**)&sent,  g_sent);
    cudaGetSymbolAddress((void**)&rev,   g_rev);
    cudaGetSymbolAddress((void**)&pbatch,g_pbatch);
    cudaGetSymbolAddress((void**)&doc,   g_doc);

    cudaFuncSetAttribute(vocab_gemm_mma, cudaFuncAttributeMaxDynamicSharedMemorySize, SMTOT);
    cudaFuncSetAttribute(word_rec_mma, cudaFuncAttributeMaxDynamicSharedMemorySize, SM_REC_TOT);

    // prep — 2 launches so word_rec_mma is our launch #4 (profiled by ncu -s 5)
    {
        int n1 = 3 * (2 * GG * 256) + 2 * DREVP * GG;
        prep1_kernel<<<(n1 + 255) / 256, 256>>>(sg_wih, sgTih, sg_whh, sgThh,
                                                rg_wih, rgTih, rg_whh, rgThh);   // launch 1
        int n2 = 2 * GG * 256 + 2 * 96 * 16 * 32 * 2 + 2 * GG;
        prep2_kernel<<<(n2 + 255) / 256, 256>>>(wg_wih, wihhi, wihlo,
                                                wg_whh, whhFhi, whhFlo,
                                                wg_bih, wg_bhh, bias_comb);      // launch 2
    }

    // word level: HMMA vocab gates (launch 3), then tensorized recurrent (launch 4)
    vocab_gemm_mma<<<dim3(NVT, 2), 256, SMTOT>>>(embed, wihhi, wihlo, bias_comb, gxv);
    word_rec_mma<<<dim3(NSENT / 32, 2), 512, SM_REC_TOT>>>(
        inputs, gxv, whhFhi, whhFlo, wg_bhh, sent);

    // sentence level
    gates_gemm_kernel<1, 256, 256, 16><<<dim3(NSENT / 16, 2), 256>>>(
        sent, sent + NSENT * HD, sgTih, sg_bih, gxs, NSENT);
    gru_rec_kernel<2, SPR><<<dim3(NREV / 2, 2), 256>>>(
        gxs, NSENT, sgThh, sg_bhh, rev, NREV);

    // p_batch + r_stars head
    pbatch_kernel<<<NREV, 288>>>(rev, rev + NREV * HD, user_feats, uf_w, pbatch);
    rstars_kernel<<<NREV, 128>>>(pbatch, rfc_w1, rfc_b1, rfc_w2, rfc_b2, out);

    // review level
    gates_gemm_kernel<2, DREVP, DREV, 16><<<dim3(NREV / 16, 2), 256>>>(
        pbatch, nullptr, rgTih, rg_bih, gxr, NREV);
    gru_rec1_kernel<<<2, 768>>>(gxr, rgThh, rg_bhh, doc);

    // p_stars head
    pstars_kernel<<<1, 128>>>(doc, pfc_w1, pfc_b1, pfc_w2, pfc_b2, out);
}

// round 15
// speedup vs baseline: 1.4830x; 1.0442x over previous
#include <cuda_runtime.h>
#include <cuda_bf16.h>
#include <math.h>

// Problem constants
#define HD 256          // hidden dim
#define GG 768          // 3*H gates
#define NV 50000        // vocabulary size
#define NVT ((NV + 127) / 128)   // vocab tiles of 128 rows (391)
#define NSENT 2048      // R*S sentences
#define NWORD 64        // words per sentence
#define NREV 64         // reviews
#define SPR 32          // sentences per review
#define DREV 276        // H + UF
#define DREVP 288       // padded
#define UF 20

typedef unsigned long long u64;
typedef unsigned int u32;
typedef unsigned short u16;

// ---------------- scratch (static device arrays; no allocation allowed) ----------------
__device__ float g_sgT_ih[2 * 256 * GG];
__device__ float g_sgT_hh[2 * 256 * GG];
__device__ float g_rgT_ih[2 * DREVP * GG];
__device__ float g_rgT_hh[2 * 256 * GG];
__device__ __nv_bfloat16 g_wih_hi[2 * GG * 256];   // split-bf16 word Wih (native [g][k])
__device__ __nv_bfloat16 g_wih_lo[2 * GG * 256];
__device__ u32 g_whhF_hi[2 * 96 * 16 * 32 * 2];    // fragment-major split Whh (hi)
__device__ u32 g_whhF_lo[2 * 96 * 16 * 32 * 2];    // fragment-major split Whh (lo)
__device__ float g_bias_comb[2 * GG];              // bih + (g<512 ? bhh : 0)
__device__ float g_gx_v[(size_t)2 * NV * GG];      // per-VOCAB input-gates (307 MB)
__device__ float g_gx_s[2 * NSENT * GG];
__device__ float g_gx_r[2 * NREV * GG];
__device__ float g_sent[2 * NSENT * HD];
__device__ float g_rev[2 * NREV * HD];
__device__ float g_pbatch[NREV * DREV];
__device__ float g_doc[2 * HD];

// ---------------- helpers ----------------
__device__ __forceinline__ float sigf(float x) { return 1.0f / (1.0f + __expf(-x)); }

__device__ __forceinline__ float seluf(float x) {
    const float alpha = 1.6732632423543772f;
    const float scale = 1.0507009873554805f;
    return x > 0.0f ? scale * x : scale * alpha * (expf(x) - 1.0f);
}

__device__ __forceinline__ u64 pack2(float lo, float hi) {
    u64 r; asm("mov.b64 %0, {%1, %2};" : "=l"(r) : "f"(lo), "f"(hi)); return r;
}
__device__ __forceinline__ void unpack2(u64 v, float& lo, float& hi) {
    asm("mov.b64 {%0, %1}, %2;" : "=f"(lo), "=f"(hi) : "l"(v));
}
__device__ __forceinline__ u64 fma2(u64 a, u64 b, u64 c) {
    u64 d; asm("fma.rn.f32x2 %0, %1, %2, %3;" : "=l"(d) : "l"(a), "l"(b), "l"(c)); return d;
}
__device__ __forceinline__ void pf_l1(const float* p) {
    asm volatile("prefetch.global.L1 [%0];" :: "l"(p));
}
__device__ __forceinline__ u32 smem_u32(const void* p) {
    u32 a; asm("{ .reg .u64 t; cvta.to.shared.u64 t, %1; cvt.u32.u64 %0, t; }" : "=r"(a) : "l"(p));
    return a;
}

// ---------------- baseline-PTX tensor core wrappers (sm_80+) ----------
__device__ __forceinline__ void ldm_x4(u32& r0, u32& r1, u32& r2, u32& r3, u32 addr) {
    asm volatile("ldmatrix.sync.aligned.m8n8.x4.shared.b16 {%0,%1,%2,%3}, [%4];"
                 : "=r"(r0), "=r"(r1), "=r"(r2), "=r"(r3) : "r"(addr));
}
__device__ __forceinline__ void mma_bf16(float* d, const u32* a, u32 b0, u32 b1) {
    asm volatile("mma.sync.aligned.m16n8k16.row.col.f32.bf16.bf16.f32 "
                 "{%0,%1,%2,%3}, {%4,%5,%6,%7}, {%8,%9}, {%0,%1,%2,%3};"
                 : "+f"(d[0]), "+f"(d[1]), "+f"(d[2]), "+f"(d[3])
                 : "r"(a[0]), "r"(a[1]), "r"(a[2]), "r"(a[3]), "r"(b0), "r"(b1));
}

// split fp32 -> (hi, lo) bf16
__device__ __forceinline__ void bf_split(float x, u16& hb, u16& lb) {
    __nv_bfloat16 h = __float2bfloat16_rn(x);
    float r = x - __bfloat162float(h);
    __nv_bfloat16 l = __float2bfloat16_rn(r);
    hb = __bfloat16_as_ushort(h);
    lb = __bfloat16_as_ushort(l);
}

// ---------------- prep 1: sg transposes + rg transposes ----------------
__global__ void prep1_kernel(const float* __restrict__ sg_wih, float* __restrict__ sgTih,
                             const float* __restrict__ sg_whh, float* __restrict__ sgThh,
                             const float* __restrict__ rg_wih, float* __restrict__ rgTih,
                             const float* __restrict__ rg_whh, float* __restrict__ rgThh) {
    const int nA = 2 * GG * 256;
    const int nB = 2 * DREVP * GG;
    int idx = blockIdx.x * blockDim.x + threadIdx.x;
    if (idx < nA) {
        int g = idx % GG; int rem = idx / GG; int k = rem % 256; int d = rem / 256;
        sgTih[idx] = sg_wih[((size_t)d * GG + g) * 256 + k];
    } else if (idx < 2 * nA) {
        int j = idx - nA;
        int g = j % GG; int rem = j / GG; int k = rem % 256; int d = rem / 256;
        sgThh[j] = sg_whh[((size_t)d * GG + g) * 256 + k];
    } else if (idx < 3 * nA) {
        int j = idx - 2 * nA;
        int g = j % GG; int rem = j / GG; int k = rem % 256; int d = rem / 256;
        rgThh[j] = rg_whh[((size_t)d * GG + g) * 256 + k];
    } else if (idx < 3 * nA + nB) {
        int j = idx - 3 * nA;
        int g = j % GG; int rem = j / GG; int k = rem % DREVP; int d = rem / DREVP;
        rgTih[j] = (k < DREV) ? rg_wih[((size_t)d * GG + g) * DREV + k] : 0.0f;
    }
}

// ---------------- prep 2: wih split + Whh fragment-major split + combined bias ----------
__global__ void prep2_kernel(const float* __restrict__ wg_wih,
                             __nv_bfloat16* __restrict__ wihhi,
                             __nv_bfloat16* __restrict__ wihlo,
                             const float* __restrict__ wg_whh,
                             u32* __restrict__ whhFhi, u32* __restrict__ whhFlo,
                             const float* __restrict__ wg_bih,
                             const float* __restrict__ wg_bhh,
                             float* __restrict__ bias_comb) {
    const int nW = 2 * GG * 256;
    const int nF = 2 * 96 * 16 * 32 * 2;
    int idx = blockIdx.x * blockDim.x + threadIdx.x;
    if (idx < nW) {
        u16 hb, lb;
        bf_split(wg_wih[idx], hb, lb);
        wihhi[idx] = __ushort_as_bfloat16(hb);
        wihlo[idx] = __ushort_as_bfloat16(lb);
    } else if (idx < nW + nF) {
        int i = idx - nW;
        int p    = i & 1;
        int lane = (i >> 1) & 31;
        int ks   = (i >> 6) & 15;
        int rest = i >> 10;
        int gt   = rest % 96;
        int dir  = rest / 96;
        int g = gt * 8 + (lane >> 2);
        int k = ks * 16 + 2 * (lane & 3) + p * 8;
        float w0 = wg_whh[((size_t)dir * GG + g) * 256 + k];
        float w1 = wg_whh[((size_t)dir * GG + g) * 256 + k + 1];
        u16 h0, l0, h1, l1;
        bf_split(w0, h0, l0); bf_split(w1, h1, l1);
        whhFhi[i] = (u32)h0 | ((u32)h1 << 16);
        whhFlo[i] = (u32)l0 | ((u32)l1 << 16);
    } else if (idx < nW + nF + 2 * GG) {
        int j = idx - nW - nF;
        int g = j % GG;
        bias_comb[j] = wg_bih[j] + (g < 512 ? wg_bhh[j] : 0.0f);
    }
}

// ================= HMMA (mma.sync) vocab input-gate GEMM =================
#define ASTRIDE 264
#define OFF_AHI 0
#define OFF_ALO (128 * ASTRIDE)
#define OFF_BHI (2 * 128 * ASTRIDE)
#define OFF_BLO (2 * 128 * ASTRIDE + 64 * ASTRIDE)
#define SMTOT   ((2 * 128 * ASTRIDE + 2 * 64 * ASTRIDE) * 2)   // 202752 bytes

__global__ __launch_bounds__(256)
void vocab_gemm_mma(const float* __restrict__ embed,
                    const __nv_bfloat16* __restrict__ whi,
                    const __nv_bfloat16* __restrict__ wlo,
                    const float* __restrict__ bias,
                    float* __restrict__ gxv) {
    extern __shared__ __nv_bfloat16 sm[];
    __nv_bfloat16* Ahi = sm + OFF_AHI;
    __nv_bfloat16* Alo = sm + OFF_ALO;
    __nv_bfloat16* Bhi = sm + OFF_BHI;
    __nv_bfloat16* Blo = sm + OFF_BLO;

    const int dir  = blockIdx.y;
    const int row0 = blockIdx.x * 128;
    const int tid  = threadIdx.x;
    const int lane = tid & 31;
    const int warp = tid >> 5;

    for (int i = tid; i < 128 * 64; i += 256) {
        int r = i >> 6, q = i & 63;
        int vr = row0 + r; if (vr >= NV) vr = NV - 1;
        float4 v = __ldg(reinterpret_cast<const float4*>(embed + (size_t)vr * HD) + q);
        u16 h0, l0, h1, l1, h2, l2, h3, l3;
        bf_split(v.x, h0, l0); bf_split(v.y, h1, l1);
        bf_split(v.z, h2, l2); bf_split(v.w, h3, l3);
        uint2 ph = make_uint2((u32)h0 | ((u32)h1 << 16), (u32)h2 | ((u32)h3 << 16));
        uint2 pl = make_uint2((u32)l0 | ((u32)l1 << 16), (u32)l2 | ((u32)l3 << 16));
        *reinterpret_cast<uint2*>(Ahi + r * ASTRIDE + q * 4) = ph;
        *reinterpret_cast<uint2*>(Alo + r * ASTRIDE + q * 4) = pl;
    }
    __syncthreads();

    const u32 aRow = warp * 16 + (lane & 15);
    const u32 aK8  = (u32)(lane >> 4) << 3;
    const u32 aHiAddr = smem_u32(Ahi + aRow * ASTRIDE + aK8);
    const u32 aLoAddr = smem_u32(Alo + aRow * ASTRIDE + aK8);
    const u32 bRow = ((u32)(lane >> 4) << 3) + (lane & 7);
    const u32 bK8  = ((u32)(lane >> 3) & 1) << 3;
    const u32 bHiAddr = smem_u32(Bhi + bRow * ASTRIDE + bK8);
    const u32 bLoAddr = smem_u32(Blo + bRow * ASTRIDE + bK8);

    const int r0 = row0 + warp * 16 + (lane >> 2);

#pragma unroll 1
    for (int ch = 0; ch < 12; ch++) {
        {
            const __nv_bfloat16* srch = whi + ((size_t)dir * GG + ch * 64) * 256;
            const __nv_bfloat16* srcl = wlo + ((size_t)dir * GG + ch * 64) * 256;
            for (int i = tid; i < 64 * 32; i += 256) {
                int r = i >> 5, q = i & 31;
                *reinterpret_cast<uint4*>(Bhi + r * ASTRIDE + q * 8) =
                    reinterpret_cast<const uint4*>(srch + (size_t)r * 256)[q];
                *reinterpret_cast<uint4*>(Blo + r * ASTRIDE + q * 8) =
                    reinterpret_cast<const uint4*>(srcl + (size_t)r * 256)[q];
            }
        }
        __syncthreads();

        float acc[8][4];
#pragma unroll
        for (int n = 0; n < 8; n++) { acc[n][0] = acc[n][1] = acc[n][2] = acc[n][3] = 0.0f; }

#pragma unroll 1
        for (int ks = 0; ks < 16; ks++) {
            u32 ah[4], al[4];
            ldm_x4(ah[0], ah[1], ah[2], ah[3], aHiAddr + ks * 32);
            ldm_x4(al[0], al[1], al[2], al[3], aLoAddr + ks * 32);
#pragma unroll
            for (int p = 0; p < 4; p++) {
                u32 bh[4], bl[4];
                const u32 boff = (u32)(p * 16) * (ASTRIDE * 2) + ks * 32;
                ldm_x4(bh[0], bh[1], bh[2], bh[3], bHiAddr + boff);
                ldm_x4(bl[0], bl[1], bl[2], bl[3], bLoAddr + boff);
                mma_bf16(acc[2 * p],     ah, bh[0], bh[1]);
                mma_bf16(acc[2 * p],     ah, bl[0], bl[1]);
                mma_bf16(acc[2 * p],     al, bh[0], bh[1]);
                mma_bf16(acc[2 * p + 1], ah, bh[2], bh[3]);
                mma_bf16(acc[2 * p + 1], ah, bl[2], bl[3]);
                mma_bf16(acc[2 * p + 1], al, bh[2], bh[3]);
            }
        }
        __syncthreads();

        const int gbase = ch * 64 + 2 * (lane & 3);
#pragma unroll
        for (int nt = 0; nt < 8; nt++) {
            const int g = gbase + nt * 8;
            const float b0 = __ldg(bias + dir * GG + g);
            const float b1 = __ldg(bias + dir * GG + g + 1);
            if (r0 < NV) {
                float2 o = make_float2(acc[nt][0] + b0, acc[nt][1] + b1);
                *reinterpret_cast<float2*>(gxv + ((size_t)dir * NV + r0) * GG + g) = o;
            }
            if (r0 + 8 < NV) {
                float2 o = make_float2(acc[nt][2] + b0, acc[nt][3] + b1);
                *reinterpret_cast<float2*>(gxv + ((size_t)dir * NV + r0 + 8) * GG + g) = o;
            }
        }
    }
}

// ================= tensorized word-level recurrent GRU (512 threads, v4) =================
// v3 + (a) double-buffered h hi/lo smem -> ONE barrier per step, (b) L1 prefetch of the
// step's gate rows before the MMA loop, (c) vocab indices cached in registers.
#define RSTR 264
#define HBUF_B (32 * RSTR * 2)                  // one hi or lo buffer = 16896 bytes
#define SM_HFP (4 * HBUF_B)                     // after 2 x (hi+lo)
#define SM_REC_TOT (4 * HBUF_B + 32 * RSTR * 4) // 101376 bytes

__global__ __launch_bounds__(512)
void word_rec_mma(const int* __restrict__ widx,
                  const float* __restrict__ gxv,
                  const u32* __restrict__ whhFhi,
                  const u32* __restrict__ whhFlo,
                  const float* __restrict__ wg_bhh,
                  float* __restrict__ sent) {
    extern __shared__ char smraw[];
    // buffer b: hi at 2*b*HBUF_B, lo at 2*b*HBUF_B + HBUF_B; hfp at SM_HFP
    float* hfp = reinterpret_cast<float*>(smraw + SM_HFP);

    const int dir  = blockIdx.y;
    const int row0 = blockIdx.x * 32;
    const int tid  = threadIdx.x;
    const int lane = tid & 31;
    const int warp = tid >> 5;   // 0..15

    for (int i = tid; i < SM_REC_TOT / 4; i += 512)
        reinterpret_cast<u32*>(smraw)[i] = 0u;
    __syncthreads();

    // A ldmatrix base addresses in buffer 0 (add 2*HBUF_B*bsel per step)
    const u32 aK8 = (u32)(lane >> 4) << 3;
    const u32 smBase = smem_u32(smraw);
    const u32 aHi0b = smBase + (((lane & 15)) * RSTR + aK8) * 2;
    const u32 aLo0b = aHi0b + HBUF_B;
    const u32 aHi1b = smBase + ((16 + (lane & 15)) * RSTR + aK8) * 2;
    const u32 aLo1b = aHi1b + HBUF_B;

    // B fragment warp base
    const char* fWhi = reinterpret_cast<const char*>(whhFhi)
                       + (size_t)dir * 96 * 4096 + (size_t)warp * 8192 + lane * 8;
    const char* fWlo = reinterpret_cast<const char*>(whhFlo)
                       + (size_t)dir * 96 * 4096 + (size_t)warp * 8192 + lane * 8;

    const float* bhhn = wg_bhh + dir * GG + 512;
    const int dbase = 16 * warp + 2 * (lane & 3);
    const float2 bn0 = *reinterpret_cast<const float2*>(bhhn + dbase);
    const float2 bn1 = *reinterpret_cast<const float2*>(bhhn + dbase + 8);

    // per-thread epilogue rows and their widx row pointers
    const int* wr[2][2];
#pragma unroll
    for (int a = 0; a < 2; a++)
#pragma unroll
        for (int p = 0; p < 2; p++)
            wr[a][p] = widx + (row0 + a * 16 + (lane >> 2) + p * 8) * NWORD;

    for (int t = 0; t < NWORD; t++) {
        const int te = dir ? (NWORD - 1 - t) : t;
        const int bsel = t & 1;
        const u32 boff = (u32)(2 * HBUF_B) * bsel;

        // ---- load this step's vocab indices + L1-prefetch their gate rows ----
        int vv[2][2];
#pragma unroll
        for (int a = 0; a < 2; a++)
#pragma unroll
            for (int p = 0; p < 2; p++) {
                const int v = __ldg(wr[a][p] + te);
                vv[a][p] = v;
                const float* gp = gxv + ((size_t)dir * NV + v) * GG + dbase;
                pf_l1(gp); pf_l1(gp + 8);
                pf_l1(gp + 256); pf_l1(gp + 264);
                pf_l1(gp + 512); pf_l1(gp + 520);
            }

        float acc[3][2][2][4];   // [grp][j][atile][frag]
#pragma unroll
        for (int g = 0; g < 3; g++)
#pragma unroll
            for (int j = 0; j < 2; j++)
#pragma unroll
                for (int a = 0; a < 2; a++)
                    acc[g][j][a][0] = acc[g][j][a][1] = acc[g][j][a][2] = acc[g][j][a][3] = 0.0f;

        u64 pb[2][12];
#pragma unroll
        for (int g = 0; g < 3; g++)
#pragma unroll
            for (int j = 0; j < 2; j++) {
                const size_t off = (size_t)g * 131072 + (size_t)j * 4096;
                pb[0][g * 4 + j * 2]     = *reinterpret_cast<const u64*>(fWhi + off);
                pb[0][g * 4 + j * 2 + 1] = *reinterpret_cast<const u64*>(fWlo + off);
            }

#pragma unroll
        for (int ks = 0; ks < 16; ks++) {
            const int cur = ks & 1, nxt = cur ^ 1;
            if (ks < 15) {
#pragma unroll
                for (int g = 0; g < 3; g++)
#pragma unroll
                    for (int j = 0; j < 2; j++) {
                        const size_t off = (size_t)g * 131072 + (size_t)j * 4096
                                         + (size_t)(ks + 1) * 256;
                        pb[nxt][g * 4 + j * 2]     = *reinterpret_cast<const u64*>(fWhi + off);
                        pb[nxt][g * 4 + j * 2 + 1] = *reinterpret_cast<const u64*>(fWlo + off);
                    }
            }
            u32 ah0[4], al0[4], ah1[4], al1[4];
            ldm_x4(ah0[0], ah0[1], ah0[2], ah0[3], aHi0b + boff + ks * 32);
            ldm_x4(al0[0], al0[1], al0[2], al0[3], aLo0b + boff + ks * 32);
            ldm_x4(ah1[0], ah1[1], ah1[2], ah1[3], aHi1b + boff + ks * 32);
            ldm_x4(al1[0], al1[1], al1[2], al1[3], aLo1b + boff + ks * 32);
#pragma unroll
            for (int g = 0; g < 3; g++)
#pragma unroll
                for (int j = 0; j < 2; j++) {
                    const u64 bh = pb[cur][g * 4 + j * 2];
                    const u64 bl = pb[cur][g * 4 + j * 2 + 1];
                    const u32 bh0 = (u32)bh, bh1 = (u32)(bh >> 32);
                    const u32 bl0 = (u32)bl, bl1 = (u32)(bl >> 32);
                    mma_bf16(acc[g][j][0], ah0, bh0, bh1);
                    mma_bf16(acc[g][j][0], ah0, bl0, bl1);
                    mma_bf16(acc[g][j][0], al0, bh0, bh1);
                    mma_bf16(acc[g][j][1], ah1, bh0, bh1);
                    mma_bf16(acc[g][j][1], ah1, bl0, bl1);
                    mma_bf16(acc[g][j][1], al1, bh0, bh1);
                }
        }

        // ---- epilogue (no barrier needed: writes go to the OTHER h buffer) ----
        __nv_bfloat16* whhi = reinterpret_cast<__nv_bfloat16*>(smraw + (bsel ^ 1) * 2 * HBUF_B);
        __nv_bfloat16* whlo = reinterpret_cast<__nv_bfloat16*>(smraw + (bsel ^ 1) * 2 * HBUF_B + HBUF_B);

#pragma unroll
        for (int a = 0; a < 2; a++) {
#pragma unroll
            for (int p = 0; p < 2; p++) {
                const int row = a * 16 + (lane >> 2) + p * 8;
                const float* gp = gxv + ((size_t)dir * NV + vv[a][p]) * GG;
#pragma unroll
                for (int j = 0; j < 2; j++) {
                    const int d = dbase + 8 * j;
                    const float2 bn = j ? bn1 : bn0;
                    float2 xr = *reinterpret_cast<const float2*>(gp + d);
                    float2 xz = *reinterpret_cast<const float2*>(gp + 256 + d);
                    float2 xn = *reinterpret_cast<const float2*>(gp + 512 + d);
                    float r0 = sigf(xr.x + acc[0][j][a][2 * p]);
                    float r1 = sigf(xr.y + acc[0][j][a][2 * p + 1]);
                    float z0 = sigf(xz.x + acc[1][j][a][2 * p]);
                    float z1 = sigf(xz.y + acc[1][j][a][2 * p + 1]);
                    float n0 = tanhf(xn.x + r0 * (acc[2][j][a][2 * p] + bn.x));
                    float n1 = tanhf(xn.y + r1 * (acc[2][j][a][2 * p + 1] + bn.y));
                    float* hp = hfp + row * RSTR + d;
                    float h0 = (1.0f - z0) * n0 + z0 * hp[0];
                    float h1 = (1.0f - z1) * n1 + z1 * hp[1];
                    hp[0] = h0; hp[1] = h1;
                    u16 hh0, hl0, hh1, hl1;
                    bf_split(h0, hh0, hl0); bf_split(h1, hh1, hl1);
                    *reinterpret_cast<u32*>(whhi + row * RSTR + d) = (u32)hh0 | ((u32)hh1 << 16);
                    *reinterpret_cast<u32*>(whlo + row * RSTR + d) = (u32)hl0 | ((u32)hl1 << 16);
                }
            }
        }
        __syncthreads();   // h(next) complete before next step's MMA reads it
    }

    for (int i = tid; i < 32 * HD; i += 512) {
        int r = i >> 8, d = i & 255;
        sent[((size_t)dir * NSENT + row0 + r) * HD + d] = hfp[r * RSTR + d];
    }
}

// ---------------- FFMA2 input-gates GEMM (sentence / review levels) ----------------
template <int U>
__device__ __forceinline__ void load_wchunk(float (&w)[3][U], const float* __restrict__ base, int kb) {
#pragma unroll
    for (int u = 0; u < U; u++) {
        const float* p = base + (size_t)(kb + u) * GG;
        w[0][u] = __ldg(p);
        w[1][u] = __ldg(p + 256);
        w[2][u] = __ldg(p + 512);
    }
}

template <int U, int P, int K>
__device__ __forceinline__ void fma_chunk(u64 (&acc)[P][3], const float (&w)[3][U],
                                          const float2 (*sx)[K], int kb) {
#pragma unroll
    for (int u = 0; u < U; u++) {
        const u64 w0p = pack2(w[0][u], w[0][u]);
        const u64 w1p = pack2(w[1][u], w[1][u]);
        const u64 w2p = pack2(w[2][u], w[2][u]);
#pragma unroll
        for (int p = 0; p < P; p++) {
            const u64 xp = *reinterpret_cast<const u64*>(&sx[p][kb + u]);
            acc[p][0] = fma2(xp, w0p, acc[p][0]);
            acc[p][1] = fma2(xp, w1p, acc[p][1]);
            acc[p][2] = fma2(xp, w2p, acc[p][2]);
        }
    }
}

// MODE 1: x = xin0[row]+xin1[row] (sentence level)
// MODE 2: x = xin0[row]  (review level, true K = KD, padded to K)
template <int MODE, int K, int KD, int TOKS>
__global__ __launch_bounds__(256, 2)
void gates_gemm_kernel(const float* __restrict__ xin0,
                       const float* __restrict__ xin1,
                       const float* __restrict__ wT_ih,
                       const float* __restrict__ bih,
                       float* __restrict__ gx, int M) {
    constexpr int P = TOKS / 2;
    constexpr int U = 4;
    const int dir  = blockIdx.y;
    const int tok0 = blockIdx.x * TOKS;
    const int t0   = threadIdx.x;

    __shared__ float2 sx2[P][K];

#pragma unroll
    for (int p = 0; p < P; p++) {
        const int ta = tok0 + 2 * p, tb = ta + 1;
        for (int k = t0; k < K; k += 256) {
            float xa, xb;
            if (MODE == 1) {
                xa = xin0[(size_t)ta * HD + k] + xin1[(size_t)ta * HD + k];
                xb = xin0[(size_t)tb * HD + k] + xin1[(size_t)tb * HD + k];
            } else {
                xa = (k < KD) ? xin0[(size_t)ta * KD + k] : 0.0f;
                xb = (k < KD) ? xin0[(size_t)tb * KD + k] : 0.0f;
            }
            sx2[p][k] = make_float2(xa, xb);
        }
    }
    __syncthreads();

    const float* wbase = wT_ih + (size_t)dir * K * GG + t0;
    u64 acc[P][3];
#pragma unroll
    for (int p = 0; p < P; p++) acc[p][0] = acc[p][1] = acc[p][2] = 0ull;

    float wA[3][U], wB[3][U];
    load_wchunk<U>(wA, wbase, 0);
#pragma unroll 1
    for (int kb = 0; kb < K; kb += 2 * U) {
        load_wchunk<U>(wB, wbase, kb + U);
        fma_chunk<U, P, K>(acc, wA, sx2, kb);
        if (kb + 2 * U < K) load_wchunk<U>(wA, wbase, kb + 2 * U);
        fma_chunk<U, P, K>(acc, wB, sx2, kb + U);
    }

    const float bi0 = bih[dir * GG + t0];
    const float bi1 = bih[dir * GG + 256 + t0];
    const float bi2 = bih[dir * GG + 512 + t0];
#pragma unroll
    for (int p = 0; p < P; p++) {
        float a0, b0, a1, b1, a2, b2;
        unpack2(acc[p][0], a0, b0);
        unpack2(acc[p][1], a1, b1);
        unpack2(acc[p][2], a2, b2);
        float* oa = gx + ((size_t)dir * M + tok0 + 2 * p) * GG;
        float* ob = oa + GG;
        oa[t0]       = a0 + bi0;  ob[t0]       = b0 + bi0;
        oa[256 + t0] = a1 + bi1;  ob[256 + t0] = b1 + bi1;
        oa[512 + t0] = a2 + bi2;  ob[512 + t0] = b2 + bi2;
    }
}

// ---------------- sentence-level recurrent GRU, row-paired f32x2 ----------------
template <int ROWS, int T>
__global__ __launch_bounds__(256, 2)
void gru_rec_kernel(const float* __restrict__ gx, int gxM,
                    const float* __restrict__ wT_hh,
                    const float* __restrict__ bhh,
                    float* __restrict__ out, int nbatch) {
    constexpr int P = ROWS / 2;
    constexpr int U = 4;
    const int dir  = blockIdx.y;
    const int row0 = blockIdx.x * ROWS;
    const int t0   = threadIdx.x;

    __shared__ float2 sh2[P][HD];
#pragma unroll
    for (int p = 0; p < P; p++) sh2[p][t0] = make_float2(0.0f, 0.0f);

    const float* wbase = wT_hh + (size_t)dir * HD * GG + t0;
    const float bh0 = bhh[dir * GG + t0];
    const float bh1 = bhh[dir * GG + 256 + t0];
    const float bh2 = bhh[dir * GG + 512 + t0];
    __syncthreads();

    for (int t = 0; t < T; t++) {
        const int te = dir ? (T - 1 - t) : t;

        u64 ah[P][3];
#pragma unroll
        for (int p = 0; p < P; p++) ah[p][0] = ah[p][1] = ah[p][2] = 0ull;

        float wA[3][U], wB[3][U];
        load_wchunk<U>(wA, wbase, 0);
#pragma unroll 1
        for (int kb = 0; kb < HD; kb += 2 * U) {
            load_wchunk<U>(wB, wbase, kb + U);
            fma_chunk<U, P, HD>(ah, wA, sh2, kb);
            if (kb + 2 * U < HD) load_wchunk<U>(wA, wbase, kb + 2 * U);
            fma_chunk<U, P, HD>(ah, wB, sh2, kb + U);
        }
        __syncthreads();

#pragma unroll
        for (int p = 0; p < P; p++) {
            const int ra = row0 + 2 * p, rb = ra + 1;
            const float* ga = gx + ((size_t)dir * gxM + (size_t)ra * T + te) * GG;
            const float* gb = gx + ((size_t)dir * gxM + (size_t)rb * T + te) * GG;
            const float x0a = ga[t0], x1a = ga[256 + t0], x2a = ga[512 + t0];
            const float x0b = gb[t0], x1b = gb[256 + t0], x2b = gb[512 + t0];
            float h0a, h0b, h1a, h1b, h2a, h2b;
            unpack2(ah[p][0], h0a, h0b); unpack2(ah[p][1], h1a, h1b); unpack2(ah[p][2], h2a, h2b);
            const float2 hold = sh2[p][t0];
            const float rga = sigf(x0a + h0a + bh0), rgb = sigf(x0b + h0b + bh0);
            const float za  = sigf(x1a + h1a + bh1), zb  = sigf(x1b + h1b + bh1);
            const float na  = tanhf(x2a + rga * (h2a + bh2));
            const float nb  = tanhf(x2b + rgb * (h2b + bh2));
            sh2[p][t0] = make_float2((1.0f - za) * na + za * hold.x,
                                     (1.0f - zb) * nb + zb * hold.y);
        }
        __syncthreads();
    }

#pragma unroll
    for (int p = 0; p < P; p++) {
        const float2 h = sh2[p][t0];
        out[((size_t)dir * nbatch + row0 + 2 * p) * HD + t0]     = h.x;
        out[((size_t)dir * nbatch + row0 + 2 * p + 1) * HD + t0] = h.y;
    }
}

// ---------------- review-level recurrent GRU (batch 1, 768 threads) -------
__global__ __launch_bounds__(768)
void gru_rec1_kernel(const float* __restrict__ gx,
                     const float* __restrict__ wT_hh,
                     const float* __restrict__ bhh,
                     float* __restrict__ out) {
    const int dir = blockIdx.x;
    const int g   = threadIdx.x;
    __shared__ float sh[HD];
    __shared__ float acc[GG];
    if (g < HD) sh[g] = 0.0f;
    const float* whh = wT_hh + (size_t)dir * HD * GG + g;
    const float bh = bhh[dir * GG + g];
    __syncthreads();

    for (int t = 0; t < NREV; t++) {
        const int te = dir ? (NREV - 1 - t) : t;
        float a = 0.0f;
#pragma unroll 8
        for (int k = 0; k < HD; k++) a += sh[k] * whh[(size_t)k * GG];
        acc[g] = a + bh;
        __syncthreads();
        if (g < HD) {
            const float* ga = gx + ((size_t)dir * NREV + te) * GG;
            const float r = sigf(ga[g]       + acc[g]);
            const float z = sigf(ga[256 + g] + acc[256 + g]);
            const float n = tanhf(ga[512 + g] + r * acc[512 + g]);
            sh[g] = (1.0f - z) * n + z * sh[g];
        }
        __syncthreads();
    }
    if (g < HD) out[dir * HD + g] = sh[g];
}

// ---------------- p_batch / heads ----------------
__global__ void pbatch_kernel(const float* __restrict__ rev0,
                              const float* __restrict__ rev1,
                              const float* __restrict__ user_feats,
                              const float* __restrict__ uf_w,
                              float* __restrict__ pbatch) {
    int b = blockIdx.x;
    int t = threadIdx.x;
    if (t < HD) {
        pbatch[b * DREV + t] = rev0[b * HD + t] + rev1[b * HD + t];
    } else {
        int lane = t - HD;
        float v = (lane < UF) ? user_feats[b * UF + lane] : 0.0f;
        float s = v * v;
#pragma unroll
        for (int o = 16; o > 0; o >>= 1) s += __shfl_xor_sync(0xffffffffu, s, o);
        float nrm = fmaxf(sqrtf(s), 1e-12f);
        if (lane < UF) pbatch[b * DREV + HD + lane] = (v / nrm) * uf_w[lane];
    }
}

__global__ void rstars_kernel(const float* __restrict__ pbatch,
                              const float* __restrict__ w1, const float* __restrict__ b1,
                              const float* __restrict__ w2, const float* __restrict__ b2,
                              float* __restrict__ out) {
    int b = blockIdx.x;
    int j = threadIdx.x;
    float s = b1[j];
    for (int k = 0; k < DREV; k++) s += pbatch[b * DREV + k] * w1[j * DREV + k];
    float a = seluf(s) * w2[j];
    __shared__ float red[128];
    red[j] = a;
    __syncthreads();
    for (int st = 64; st > 0; st >>= 1) {
        if (j < st) red[j] += red[j + st];
        __syncthreads();
    }
    if (j == 0) out[9 + b] = red[0] + b2[0];
}

__global__ void pstars_kernel(const float* __restrict__ doc,
                              const float* __restrict__ w1, const float* __restrict__ b1,
                              const float* __restrict__ w2, const float* __restrict__ b2,
                              float* __restrict__ out) {
    int j = threadIdx.x;
    __shared__ float hid[128];
    float s = b1[j];
    for (int k = 0; k < HD; k++) s += (doc[k] + doc[HD + k]) * w1[j * HD + k];
    hid[j] = seluf(s);
    __syncthreads();
    if (j < 9) {
        float o = b2[j];
        for (int k = 0; k < 128; k++) o += hid[k] * w2[j * 128 + k];
        out[j] = o;
    }
}

// ---------------- launch ----------------
extern "C" void kernel_launch(void* const* d_in, const int* in_sizes, int n_in,
                              void* d_out, int out_size) {
    (void)in_sizes; (void)n_in; (void)out_size;
    const int*   inputs     = (const int*)d_in[0];
    const float* user_feats = (const float*)d_in[3];
    const float* embed      = (const float*)d_in[4];
    const float* wg_wih = (const float*)d_in[5];
    const float* wg_whh = (const float*)d_in[6];
    const float* wg_bih = (const float*)d_in[7];
    const float* wg_bhh = (const float*)d_in[8];
    const float* sg_wih = (const float*)d_in[9];
    const float* sg_whh = (const float*)d_in[10];
    const float* sg_bih = (const float*)d_in[11];
    const float* sg_bhh = (const float*)d_in[12];
    const float* rg_wih = (const float*)d_in[13];
    const float* rg_whh = (const float*)d_in[14];
    const float* rg_bih = (const float*)d_in[15];
    const float* rg_bhh = (const float*)d_in[16];
    const float* rfc_w1 = (const float*)d_in[17];
    const float* rfc_b1 = (const float*)d_in[18];
    const float* rfc_w2 = (const float*)d_in[19];
    const float* rfc_b2 = (const float*)d_in[20];
    const float* pfc_w1 = (const float*)d_in[21];
    const float* pfc_b1 = (const float*)d_in[22];
    const float* pfc_w2 = (const float*)d_in[23];
    const float* pfc_b2 = (const float*)d_in[24];
    const float* uf_w   = (const float*)d_in[25];
    float* out = (float*)d_out;

    float *sgTih, *sgThh, *rgTih, *rgThh, *bias_comb;
    float *gxv, *gxs, *gxr, *sent, *rev, *pbatch, *doc;
    __nv_bfloat16 *wihhi, *wihlo;
    u32 *whhFhi, *whhFlo;
    cudaGetSymbolAddress((void**)&sgTih, g_sgT_ih);
    cudaGetSymbolAddress((void**)&sgThh, g_sgT_hh);
    cudaGetSymbolAddress((void**)&rgTih, g_rgT_ih);
    cudaGetSymbolAddress((void**)&rgThh, g_rgT_hh);
    cudaGetSymbolAddress((void**)&wihhi, g_wih_hi);
    cudaGetSymbolAddress((void**)&wihlo, g_wih_lo);
    cudaGetSymbolAddress((void**)&whhFhi, g_whhF_hi);
    cudaGetSymbolAddress((void**)&whhFlo, g_whhF_lo);
    cudaGetSymbolAddress((void**)&bias_comb, g_bias_comb);
    cudaGetSymbolAddress((void**)&gxv,   g_gx_v);
    cudaGetSymbolAddress((void**)&gxs,   g_gx_s);
    cudaGetSymbolAddress((void**)&gxr,   g_gx_r);
    cudaGetSymbolAddress((void**)&sent,  g_sent);
    cudaGetSymbolAddress((void**)&rev,   g_rev);
    cudaGetSymbolAddress((void**)&pbatch,g_pbatch);
    cudaGetSymbolAddress((void**)&doc,   g_doc);

    cudaFuncSetAttribute(vocab_gemm_mma, cudaFuncAttributeMaxDynamicSharedMemorySize, SMTOT);
    cudaFuncSetAttribute(word_rec_mma, cudaFuncAttributeMaxDynamicSharedMemorySize, SM_REC_TOT);

    // prep — 2 launches so word_rec_mma is our launch #4 (profiled by ncu -s 5)
    {
        int n1 = 3 * (2 * GG * 256) + 2 * DREVP * GG;
        prep1_kernel<<<(n1 + 255) / 256, 256>>>(sg_wih, sgTih, sg_whh, sgThh,
                                                rg_wih, rgTih, rg_whh, rgThh);   // launch 1
        int n2 = 2 * GG * 256 + 2 * 96 * 16 * 32 * 2 + 2 * GG;
        prep2_kernel<<<(n2 + 255) / 256, 256>>>(wg_wih, wihhi, wihlo,
                                                wg_whh, whhFhi, whhFlo,
                                                wg_bih, wg_bhh, bias_comb);      // launch 2
    }

    // word level: HMMA vocab gates (launch 3), then tensorized recurrent (launch 4)
    vocab_gemm_mma<<<dim3(NVT, 2), 256, SMTOT>>>(embed, wihhi, wihlo, bias_comb, gxv);
    word_rec_mma<<<dim3(NSENT / 32, 2), 512, SM_REC_TOT>>>(
        inputs, gxv, whhFhi, whhFlo, wg_bhh, sent);

    // sentence level
    gates_gemm_kernel<1, 256, 256, 16><<<dim3(NSENT / 16, 2), 256>>>(
        sent, sent + NSENT * HD, sgTih, sg_bih, gxs, NSENT);
    gru_rec_kernel<2, SPR><<<dim3(NREV / 2, 2), 256>>>(
        gxs, NSENT, sgThh, sg_bhh, rev, NREV);

    // p_batch + r_stars head
    pbatch_kernel<<<NREV, 288>>>(rev, rev + NREV * HD, user_feats, uf_w, pbatch);
    rstars_kernel<<<NREV, 128>>>(pbatch, rfc_w1, rfc_b1, rfc_w2, rfc_b2, out);

    // review level
    gates_gemm_kernel<2, DREVP, DREV, 16><<<dim3(NREV / 16, 2), 256>>>(
        pbatch, nullptr, rgTih, rg_bih, gxr, NREV);
    gru_rec1_kernel<<<2, 768>>>(gxr, rgThh, rg_bhh, doc);

    // p_stars head
    pstars_kernel<<<1, 128>>>(doc, pfc_w1, pfc_b1, pfc_w2, pfc_b2, out);
}